// round 3
// baseline (speedup 1.0000x reference)
#include <cuda_runtime.h>
#include <math.h>

// Problem dims
#define BB 8
#define HH 256
#define WW 256
#define CC 256
#define MROWS (BB*HH*WW)        // 524288 pixel rows
#define NBH   (BB*HH)           // 2048 attention slices

// Scratch for q,k,v (512MB each) — __device__ globals (allocation rules)
__device__ float g_q[(size_t)MROWS * CC];
__device__ float g_k[(size_t)MROWS * CC];
__device__ float g_v[(size_t)MROWS * CC];

// ---------------------------------------------------------------------------
// Kernel 1: QKV projection.  out[m,n] = sum_c x[m,c]*w[c,n] + b[n]
// CTA tile: 64 rows x 256 cols (full N), K-chunks of 32.
// Thread grid 16x16; thread tile 4 rows x 16 cols (row = ty+16i, col = tx+16n).
// ---------------------------------------------------------------------------
__global__ __launch_bounds__(256, 2)
void qkv_kernel(const float* __restrict__ x,
                const float* __restrict__ wq, const float* __restrict__ bq,
                const float* __restrict__ wk, const float* __restrict__ bk,
                const float* __restrict__ wv, const float* __restrict__ bv)
{
    __shared__ float As[64][33];    // x tile, +1 pad -> conflict-free column access
    __shared__ float Bs[32][256];   // w tile

    const int sel = blockIdx.y;
    const float* __restrict__ w    = (sel == 0) ? wq : (sel == 1) ? wk : wv;
    const float* __restrict__ bias = (sel == 0) ? bq : (sel == 1) ? bk : bv;
    float* __restrict__ outp       = (sel == 0) ? g_q : (sel == 1) ? g_k : g_v;

    const int m0  = blockIdx.x * 64;
    const int tid = threadIdx.x;
    const int tx  = tid & 15;
    const int ty  = tid >> 4;

    float acc[4][16];
#pragma unroll
    for (int i = 0; i < 4; i++)
#pragma unroll
        for (int n = 0; n < 16; n++) acc[i][n] = 0.f;

    for (int kt = 0; kt < CC; kt += 32) {
        __syncthreads();
        // load x tile 64x32 (float4 coalesced; scalar STS, conflict-free pattern)
#pragma unroll
        for (int t = 0; t < 2; t++) {
            int p  = tid + 256 * t;          // 0..511 float4 slots
            int r  = p >> 3;                 // row 0..63
            int c4 = p & 7;                  // 0..7
            float4 v4 = *(const float4*)&x[(size_t)(m0 + r) * CC + kt + c4 * 4];
            As[r][c4 * 4 + 0] = v4.x;
            As[r][c4 * 4 + 1] = v4.y;
            As[r][c4 * 4 + 2] = v4.z;
            As[r][c4 * 4 + 3] = v4.w;
        }
        // load w tile 32x256 (float4 both sides)
#pragma unroll
        for (int t = 0; t < 8; t++) {
            int p  = tid + 256 * t;          // 0..2047
            int r  = p >> 6;
            int c4 = p & 63;
            *(float4*)&Bs[r][c4 * 4] =
                *(const float4*)&w[(size_t)(kt + r) * CC + c4 * 4];
        }
        __syncthreads();

#pragma unroll 4
        for (int k = 0; k < 32; k++) {
            float a[4], b[16];
#pragma unroll
            for (int i = 0; i < 4; i++) a[i] = As[ty + 16 * i][k];
#pragma unroll
            for (int n = 0; n < 16; n++) b[n] = Bs[k][tx + 16 * n];
#pragma unroll
            for (int i = 0; i < 4; i++)
#pragma unroll
                for (int n = 0; n < 16; n++) acc[i][n] += a[i] * b[n];
        }
    }

#pragma unroll
    for (int n = 0; n < 16; n++) {
        int c = tx + 16 * n;
        float bb = bias[c];
#pragma unroll
        for (int i = 0; i < 4; i++) {
            outp[(size_t)(m0 + ty + 16 * i) * CC + c] = acc[i][n] + bb;
        }
    }
}

// ---------------------------------------------------------------------------
// Kernel 2: attention per (b,h) slice + fused residual epilogue.
// smem tiles use row stride 257 (odd) -> conflict-free column access.
// ---------------------------------------------------------------------------
#define STR 257
#define TILE_FLOATS (64 * STR)
#define SMEM_FLOATS (3 * TILE_FLOATS + 256)
#define SMEM_BYTES  (SMEM_FLOATS * 4)

// load a 64x256 fp32 tile from global (row-major) into smem with stride STR.
// Warp covers 4 rows x 8 float4 chunks -> coalesced LDG + conflict-free STS.
__device__ __forceinline__ void load_tile(float* __restrict__ dst,
                                          const float* __restrict__ src,
                                          int tid)
{
#pragma unroll
    for (int t = 0; t < 16; t++) {
        int p  = tid + 256 * t;                       // 0..4095 float4 slots
        int r  = (p >> 3) & 63;                       // row
        int c4 = (p & 7) | ((p >> 9) << 3);           // 0..63
        float4 v4 = *(const float4*)&src[(size_t)r * CC + c4 * 4];
        float* d = dst + (size_t)r * STR + c4 * 4;
        d[0] = v4.x; d[1] = v4.y; d[2] = v4.z; d[3] = v4.w;
    }
}

__global__ __launch_bounds__(256, 1)
void attn_kernel(const float* __restrict__ xin,
                 const float* __restrict__ gamma,
                 float* __restrict__ out)
{
    extern __shared__ float smem[];
    float* Qs  = smem;
    float* KVs = smem + TILE_FLOATS;
    float* Ss  = smem + 2 * TILE_FLOATS;
    float* red = smem + 3 * TILE_FLOATS;   // 4 x 64 partials

    const int bh = blockIdx.x;
    const size_t base = (size_t)bh * WW * CC;   // element offset of row 0 of slice
    const int tid = threadIdx.x;
    const int tx  = tid & 15;
    const int ty  = tid >> 4;

    for (int qb = 0; qb < 4; qb++) {
        __syncthreads();
        load_tile(Qs, g_q + base + (size_t)qb * 64 * CC, tid);

        // ---- S = Q K^T  (64 q-rows x 256 k-rows), tiled over k-rows ----
        for (int kt = 0; kt < 4; kt++) {
            __syncthreads();   // prior KVs readers done (and Qs fill visible at kt=0)
            load_tile(KVs, g_k + base + (size_t)kt * 64 * CC, tid);
            __syncthreads();

            float acc[4][4];
#pragma unroll
            for (int i = 0; i < 4; i++)
#pragma unroll
                for (int n = 0; n < 4; n++) acc[i][n] = 0.f;

#pragma unroll 4
            for (int kk = 0; kk < CC; kk++) {
                float a[4], b[4];
#pragma unroll
                for (int i = 0; i < 4; i++) a[i] = Qs[(ty + 16 * i) * STR + kk];
#pragma unroll
                for (int n = 0; n < 4; n++) b[n] = KVs[(tx + 16 * n) * STR + kk];
#pragma unroll
                for (int i = 0; i < 4; i++)
#pragma unroll
                    for (int n = 0; n < 4; n++) acc[i][n] += a[i] * b[n];
            }
#pragma unroll
            for (int i = 0; i < 4; i++)
#pragma unroll
                for (int n = 0; n < 4; n++)
                    Ss[(ty + 16 * i) * STR + kt * 64 + tx + 16 * n] = acc[i][n];
        }
        __syncthreads();

        // ---- row softmax over Ss[64][256] ----
        {
            int row = tid & 63;
            int seg = tid >> 6;                  // 4 column segments of 64
            float* srow = Ss + (size_t)row * STR + seg * 64;

            float m = -1e30f;
#pragma unroll 8
            for (int c = 0; c < 64; c++) m = fmaxf(m, srow[c]);
            red[seg * 64 + row] = m;
            __syncthreads();
            m = fmaxf(fmaxf(red[row], red[64 + row]),
                      fmaxf(red[128 + row], red[192 + row]));
            __syncthreads();                     // before red reuse

            float s = 0.f;
#pragma unroll 8
            for (int c = 0; c < 64; c++) {
                float e = __expf(srow[c] - m);
                srow[c] = e;
                s += e;
            }
            red[seg * 64 + row] = s;
            __syncthreads();
            s = red[row] + red[64 + row] + red[128 + row] + red[192 + row];
            float inv = 1.f / s;
#pragma unroll 8
            for (int c = 0; c < 64; c++) srow[c] *= inv;
        }

        // ---- O = P V  (64 x 256), accumulate over 4 V tiles ----
        float oacc[4][16];
#pragma unroll
        for (int i = 0; i < 4; i++)
#pragma unroll
            for (int n = 0; n < 16; n++) oacc[i][n] = 0.f;

        for (int jt = 0; jt < 4; jt++) {
            __syncthreads();   // Ss normalize done / prior KVs readers done
            load_tile(KVs, g_v + base + (size_t)jt * 64 * CC, tid);
            __syncthreads();

#pragma unroll 4
            for (int jj = 0; jj < 64; jj++) {
                float a[4], b[16];
#pragma unroll
                for (int i = 0; i < 4; i++)
                    a[i] = Ss[(ty + 16 * i) * STR + jt * 64 + jj];
#pragma unroll
                for (int n = 0; n < 16; n++)
                    b[n] = KVs[jj * STR + tx + 16 * n];
#pragma unroll
                for (int i = 0; i < 4; i++)
#pragma unroll
                    for (int n = 0; n < 16; n++) oacc[i][n] += a[i] * b[n];
            }
        }

        // ---- epilogue: out = gamma * O + x ----
#pragma unroll
        for (int n = 0; n < 16; n++) {
            int c = tx + 16 * n;
            float g = gamma[c];
#pragma unroll
            for (int i = 0; i < 4; i++) {
                size_t off = base + (size_t)(qb * 64 + ty + 16 * i) * CC + c;
                out[off] = g * oacc[i][n] + xin[off];
            }
        }
    }
}

// ---------------------------------------------------------------------------
extern "C" void kernel_launch(void* const* d_in, const int* in_sizes, int n_in,
                              void* d_out, int out_size)
{
    const float* x     = (const float*)d_in[0];
    const float* wq    = (const float*)d_in[1];
    const float* bq    = (const float*)d_in[2];
    const float* wk    = (const float*)d_in[3];
    const float* bk    = (const float*)d_in[4];
    const float* wv    = (const float*)d_in[5];
    const float* bv    = (const float*)d_in[6];
    const float* gamma = (const float*)d_in[7];
    float* out = (float*)d_out;

    // idempotent, cheap; legal during graph capture (not a stream op)
    cudaFuncSetAttribute(attn_kernel,
                         cudaFuncAttributeMaxDynamicSharedMemorySize, SMEM_BYTES);

    dim3 g1(MROWS / 64, 3);
    qkv_kernel<<<g1, 256>>>(x, wq, bq, wk, bk, wv, bv);
    attn_kernel<<<NBH, 256, SMEM_BYTES>>>(x, gamma, out);
}

// round 4
// speedup vs baseline: 1.1903x; 1.1903x over previous
#include <cuda_runtime.h>
#include <math.h>

// Problem dims
#define BB 8
#define HH 256
#define WW 256
#define CC 256
#define MROWS (BB*HH*WW)        // 524288 pixel rows
#define NBH   (BB*HH)           // 2048 attention slices

typedef unsigned long long u64;

// Scratch for q,k,v (512MB each) — __device__ globals (allocation rules)
__device__ float g_q[(size_t)MROWS * CC];
__device__ float g_k[(size_t)MROWS * CC];
__device__ float g_v[(size_t)MROWS * CC];

// ---- packed fp32x2 helpers (sm_103a dual-FP32 path; ptxas won't auto-fuse) ----
__device__ __forceinline__ u64 pack2(float lo, float hi) {
    u64 r; asm("mov.b64 %0, {%1, %2};" : "=l"(r) : "f"(lo), "f"(hi)); return r;
}
__device__ __forceinline__ float2 unpack2(u64 v) {
    float2 r; asm("mov.b64 {%0, %1}, %2;" : "=f"(r.x), "=f"(r.y) : "l"(v)); return r;
}
__device__ __forceinline__ void ffma2(u64& d, u64 a, u64 b) {
    asm("fma.rn.f32x2 %0, %1, %2, %0;" : "+l"(d) : "l"(a), "l"(b));
}

// ---------------------------------------------------------------------------
// Kernel 1: QKV projection.  out[m,n] = sum_c x[m,c]*w[c,n] + b[n]
// CTA tile: 64 rows x 256 cols, K-chunks of 32.
// Thread tile: 4 rows x 8 column-PAIRS (col = 2*tx + 32*n) via fp32x2 FMA.
// ---------------------------------------------------------------------------
__global__ __launch_bounds__(256, 2)
void qkv_kernel(const float* __restrict__ x,
                const float* __restrict__ wq, const float* __restrict__ bq,
                const float* __restrict__ wk, const float* __restrict__ bk,
                const float* __restrict__ wv, const float* __restrict__ bv)
{
    __shared__ float As[64][33];    // x tile, +1 pad
    __shared__ float Bs[32][256];   // w tile (row = k, 1KB-aligned rows)

    const int sel = blockIdx.y;
    const float* __restrict__ w    = (sel == 0) ? wq : (sel == 1) ? wk : wv;
    const float* __restrict__ bias = (sel == 0) ? bq : (sel == 1) ? bk : bv;
    float* __restrict__ outp       = (sel == 0) ? g_q : (sel == 1) ? g_k : g_v;

    const int m0  = blockIdx.x * 64;
    const int tid = threadIdx.x;
    const int tx  = tid & 15;
    const int ty  = tid >> 4;

    u64 acc2[4][8];
#pragma unroll
    for (int i = 0; i < 4; i++)
#pragma unroll
        for (int n = 0; n < 8; n++) acc2[i][n] = 0ull;

    for (int kt = 0; kt < CC; kt += 32) {
        __syncthreads();
        // x tile 64x32
#pragma unroll
        for (int t = 0; t < 2; t++) {
            int p  = tid + 256 * t;
            int r  = p >> 3;
            int c4 = p & 7;
            float4 v4 = *(const float4*)&x[(size_t)(m0 + r) * CC + kt + c4 * 4];
            As[r][c4 * 4 + 0] = v4.x;
            As[r][c4 * 4 + 1] = v4.y;
            As[r][c4 * 4 + 2] = v4.z;
            As[r][c4 * 4 + 3] = v4.w;
        }
        // w tile 32x256
#pragma unroll
        for (int t = 0; t < 8; t++) {
            int p  = tid + 256 * t;
            int r  = p >> 6;
            int c4 = p & 63;
            *(float4*)&Bs[r][c4 * 4] =
                *(const float4*)&w[(size_t)(kt + r) * CC + c4 * 4];
        }
        __syncthreads();

#pragma unroll 4
        for (int k = 0; k < 32; k++) {
            u64 a2[4], b2[8];
#pragma unroll
            for (int i = 0; i < 4; i++) {
                float a = As[ty + 16 * i][k];
                a2[i] = pack2(a, a);
            }
#pragma unroll
            for (int n = 0; n < 8; n++)
                b2[n] = *(const u64*)&Bs[k][2 * tx + 32 * n];   // 8B-aligned
#pragma unroll
            for (int i = 0; i < 4; i++)
#pragma unroll
                for (int n = 0; n < 8; n++) ffma2(acc2[i][n], a2[i], b2[n]);
        }
    }

#pragma unroll
    for (int n = 0; n < 8; n++) {
        int c = 2 * tx + 32 * n;
        float2 bb = *(const float2*)&bias[c];
#pragma unroll
        for (int i = 0; i < 4; i++) {
            float2 v = unpack2(acc2[i][n]);
            v.x += bb.x; v.y += bb.y;
            *(float2*)&outp[(size_t)(m0 + ty + 16 * i) * CC + c] = v;
        }
    }
}

// ---------------------------------------------------------------------------
// Kernel 2: attention per (b,h) slice + fused residual epilogue.
// Q/K/V smem tiles: row stride 258 (even, ≡2 mod 4 → conflict-free 64-bit LDS).
// Ss tile: row stride 257 (scalar softmax access stays conflict-free).
// ---------------------------------------------------------------------------
#define QSTR 258
#define SSTR 257
#define QTILE_FLOATS (64 * QSTR)          // 16512
#define STILE_FLOATS (64 * SSTR)          // 16448
#define SMEM_FLOATS  (2 * QTILE_FLOATS + STILE_FLOATS + 256)
#define SMEM_BYTES   (SMEM_FLOATS * 4)

// load a 64x256 fp32 tile from global (row-major) into smem with stride QSTR.
__device__ __forceinline__ void load_tile(float* __restrict__ dst,
                                          const float* __restrict__ src,
                                          int tid)
{
#pragma unroll
    for (int t = 0; t < 16; t++) {
        int p  = tid + 256 * t;                       // 0..4095 float4 slots
        int r  = (p >> 3) & 63;                       // row
        int c4 = (p & 7) | ((p >> 9) << 3);           // 0..63
        float4 v4 = *(const float4*)&src[(size_t)r * CC + c4 * 4];
        float* d = dst + (size_t)r * QSTR + c4 * 4;
        d[0] = v4.x; d[1] = v4.y; d[2] = v4.z; d[3] = v4.w;
    }
}

__global__ __launch_bounds__(256, 1)
void attn_kernel(const float* __restrict__ xin,
                 const float* __restrict__ gamma,
                 float* __restrict__ out)
{
    extern __shared__ float smem[];
    float* Qs  = smem;
    float* KVs = smem + QTILE_FLOATS;
    float* Ss  = smem + 2 * QTILE_FLOATS;
    float* red = smem + 2 * QTILE_FLOATS + STILE_FLOATS;   // 4 x 64 partials

    const int bh = blockIdx.x;
    const size_t base = (size_t)bh * WW * CC;
    const int tid = threadIdx.x;
    const int tx  = tid & 15;
    const int ty  = tid >> 4;

    for (int qb = 0; qb < 4; qb++) {
        __syncthreads();
        load_tile(Qs, g_q + base + (size_t)qb * 64 * CC, tid);

        // ---- S = Q K^T  (64 q-rows x 256 k-rows), packed over reduction dim ----
        for (int kt = 0; kt < 4; kt++) {
            __syncthreads();
            load_tile(KVs, g_k + base + (size_t)kt * 64 * CC, tid);
            __syncthreads();

            u64 acc2[4][4];
#pragma unroll
            for (int i = 0; i < 4; i++)
#pragma unroll
                for (int n = 0; n < 4; n++) acc2[i][n] = 0ull;

#pragma unroll 4
            for (int kk = 0; kk < CC; kk += 2) {
                u64 a2[4], b2[4];
#pragma unroll
                for (int i = 0; i < 4; i++)
                    a2[i] = *(const u64*)&Qs[(ty + 16 * i) * QSTR + kk];   // broadcast
#pragma unroll
                for (int n = 0; n < 4; n++)
                    b2[n] = *(const u64*)&KVs[(tx + 16 * n) * QSTR + kk];  // conflict-free
#pragma unroll
                for (int i = 0; i < 4; i++)
#pragma unroll
                    for (int n = 0; n < 4; n++) ffma2(acc2[i][n], a2[i], b2[n]);
            }
#pragma unroll
            for (int i = 0; i < 4; i++)
#pragma unroll
                for (int n = 0; n < 4; n++) {
                    float2 s = unpack2(acc2[i][n]);
                    Ss[(ty + 16 * i) * SSTR + kt * 64 + tx + 16 * n] = s.x + s.y;
                }
        }
        __syncthreads();

        // ---- row softmax over Ss[64][256] ----
        {
            int row = tid & 63;
            int seg = tid >> 6;
            float* srow = Ss + (size_t)row * SSTR + seg * 64;

            float m = -1e30f;
#pragma unroll 8
            for (int c = 0; c < 64; c++) m = fmaxf(m, srow[c]);
            red[seg * 64 + row] = m;
            __syncthreads();
            m = fmaxf(fmaxf(red[row], red[64 + row]),
                      fmaxf(red[128 + row], red[192 + row]));
            __syncthreads();

            float s = 0.f;
#pragma unroll 8
            for (int c = 0; c < 64; c++) {
                float e = __expf(srow[c] - m);
                srow[c] = e;
                s += e;
            }
            red[seg * 64 + row] = s;
            __syncthreads();
            s = red[row] + red[64 + row] + red[128 + row] + red[192 + row];
            float inv = 1.f / s;
#pragma unroll 8
            for (int c = 0; c < 64; c++) srow[c] *= inv;
        }

        // ---- O = P V  (64 x 256), packed over output-column pairs ----
        u64 oacc2[4][8];
#pragma unroll
        for (int i = 0; i < 4; i++)
#pragma unroll
            for (int n = 0; n < 8; n++) oacc2[i][n] = 0ull;

        for (int jt = 0; jt < 4; jt++) {
            __syncthreads();
            load_tile(KVs, g_v + base + (size_t)jt * 64 * CC, tid);
            __syncthreads();

#pragma unroll 4
            for (int jj = 0; jj < 64; jj++) {
                u64 a2[4], b2[8];
#pragma unroll
                for (int i = 0; i < 4; i++) {
                    float a = Ss[(ty + 16 * i) * SSTR + jt * 64 + jj];     // broadcast
                    a2[i] = pack2(a, a);
                }
#pragma unroll
                for (int n = 0; n < 8; n++)
                    b2[n] = *(const u64*)&KVs[jj * QSTR + 2 * tx + 32 * n];
#pragma unroll
                for (int i = 0; i < 4; i++)
#pragma unroll
                    for (int n = 0; n < 8; n++) ffma2(oacc2[i][n], a2[i], b2[n]);
            }
        }

        // ---- epilogue: out = gamma * O + x  (float2 path) ----
#pragma unroll
        for (int n = 0; n < 8; n++) {
            int c = 2 * tx + 32 * n;
            float2 g = *(const float2*)&gamma[c];
#pragma unroll
            for (int i = 0; i < 4; i++) {
                size_t off = base + (size_t)(qb * 64 + ty + 16 * i) * CC + c;
                float2 o  = unpack2(oacc2[i][n]);
                float2 xi = *(const float2*)&xin[off];
                float2 r;
                r.x = g.x * o.x + xi.x;
                r.y = g.y * o.y + xi.y;
                *(float2*)&out[off] = r;
            }
        }
    }
}

// ---------------------------------------------------------------------------
extern "C" void kernel_launch(void* const* d_in, const int* in_sizes, int n_in,
                              void* d_out, int out_size)
{
    const float* x     = (const float*)d_in[0];
    const float* wq    = (const float*)d_in[1];
    const float* bq    = (const float*)d_in[2];
    const float* wk    = (const float*)d_in[3];
    const float* bk    = (const float*)d_in[4];
    const float* wv    = (const float*)d_in[5];
    const float* bv    = (const float*)d_in[6];
    const float* gamma = (const float*)d_in[7];
    float* out = (float*)d_out;

    cudaFuncSetAttribute(attn_kernel,
                         cudaFuncAttributeMaxDynamicSharedMemorySize, SMEM_BYTES);

    dim3 g1(MROWS / 64, 3);
    qkv_kernel<<<g1, 256>>>(x, wq, bq, wk, bk, wv, bv);
    attn_kernel<<<NBH, 256, SMEM_BYTES>>>(x, gamma, out);
}

// round 9
// speedup vs baseline: 1.7648x; 1.4826x over previous
#include <cuda_runtime.h>
#include <cuda_bf16.h>
#include <math.h>
#include <stdint.h>

// Problem dims
#define BB 8
#define HH 256
#define WW 256
#define CC 256
#define MROWS (BB*HH*WW)        // 524288 pixel rows
#define NBH   (BB*HH)           // 2048 attention slices

typedef unsigned long long u64;

// ---------------- device scratch (allocation rules: __device__ globals) ------
__device__ float g_q[(size_t)MROWS * CC];
__device__ float g_k[(size_t)MROWS * CC];
__device__ float g_v[(size_t)MROWS * CC];
__device__ __nv_bfloat162 g_xhi[(size_t)MROWS * CC / 2];
__device__ __nv_bfloat162 g_xlo[(size_t)MROWS * CC / 2];
__device__ __nv_bfloat16  g_wthi[3 * CC * CC];   // w^T hi  [sel][n][k]
__device__ __nv_bfloat16  g_wtlo[3 * CC * CC];   // w^T lo

// ---------------- warp-mma helpers (baseline PTX, no arch-'a' features) ------
__device__ __forceinline__ uint32_t smem_to_u32(const void* p) {
    uint32_t a;
    asm("{ .reg .u64 t; cvta.to.shared.u64 t, %1; cvt.u32.u64 %0, t; }"
        : "=r"(a) : "l"(p));
    return a;
}
__device__ __forceinline__ void ldm4(uint32_t* r, uint32_t addr) {
    asm volatile("ldmatrix.sync.aligned.m8n8.x4.shared.b16 {%0,%1,%2,%3}, [%4];"
                 : "=r"(r[0]), "=r"(r[1]), "=r"(r[2]), "=r"(r[3]) : "r"(addr));
}
__device__ __forceinline__ void mma16816(float* c, const uint32_t* a, const uint32_t* b) {
    asm volatile("mma.sync.aligned.m16n8k16.row.col.f32.bf16.bf16.f32 "
                 "{%0,%1,%2,%3}, {%4,%5,%6,%7}, {%8,%9}, {%0,%1,%2,%3};"
                 : "+f"(c[0]), "+f"(c[1]), "+f"(c[2]), "+f"(c[3])
                 : "r"(a[0]), "r"(a[1]), "r"(a[2]), "r"(a[3]),
                   "r"(b[0]), "r"(b[1]));
}

// ---- packed fp32x2 helpers (attn kernel) ------------------------------------
__device__ __forceinline__ u64 pack2(float lo, float hi) {
    u64 r; asm("mov.b64 %0, {%1, %2};" : "=l"(r) : "f"(lo), "f"(hi)); return r;
}
__device__ __forceinline__ float2 unpack2(u64 v) {
    float2 r; asm("mov.b64 {%0, %1}, %2;" : "=f"(r.x), "=f"(r.y) : "l"(v)); return r;
}
__device__ __forceinline__ void ffma2(u64& d, u64 a, u64 b) {
    asm("fma.rn.f32x2 %0, %1, %2, %0;" : "+l"(d) : "l"(a), "l"(b));
}

// ---------------------------------------------------------------------------
// Convert kernels: x -> bf16 hi/lo, w -> transposed bf16 hi/lo
// ---------------------------------------------------------------------------
__global__ __launch_bounds__(256)
void cvt_x_kernel(const float* __restrict__ x)
{
    size_t i = (size_t)blockIdx.x * 256 + threadIdx.x;   // float4 index
    float4 v = ((const float4*)x)[i];
    __nv_bfloat16 h0 = __float2bfloat16(v.x);
    __nv_bfloat16 h1 = __float2bfloat16(v.y);
    __nv_bfloat16 h2 = __float2bfloat16(v.z);
    __nv_bfloat16 h3 = __float2bfloat16(v.w);
    __nv_bfloat16 l0 = __float2bfloat16(v.x - __bfloat162float(h0));
    __nv_bfloat16 l1 = __float2bfloat16(v.y - __bfloat162float(h1));
    __nv_bfloat16 l2 = __float2bfloat16(v.z - __bfloat162float(h2));
    __nv_bfloat16 l3 = __float2bfloat16(v.w - __bfloat162float(h3));
    g_xhi[i * 2 + 0] = __halves2bfloat162(h0, h1);
    g_xhi[i * 2 + 1] = __halves2bfloat162(h2, h3);
    g_xlo[i * 2 + 0] = __halves2bfloat162(l0, l1);
    g_xlo[i * 2 + 1] = __halves2bfloat162(l2, l3);
}

__global__ __launch_bounds__(256)
void cvt_w_kernel(const float* __restrict__ wq,
                  const float* __restrict__ wk,
                  const float* __restrict__ wv)
{
    int sel = blockIdx.y;
    const float* w = (sel == 0) ? wq : (sel == 1) ? wk : wv;
    int k = blockIdx.x;          // 0..255
    int n = threadIdx.x;         // 0..255
    float a = w[k * CC + n];     // coalesced read
    __nv_bfloat16 h = __float2bfloat16(a);
    __nv_bfloat16 l = __float2bfloat16(a - __bfloat162float(h));
    g_wthi[sel * CC * CC + n * CC + k] = h;   // transposed store
    g_wtlo[sel * CC * CC + n * CC + k] = l;
}

// ---------------------------------------------------------------------------
// QKV GEMM via warp-level mma.sync (bf16x3 split, fp32 accum).
// CTA: M=128 x N=128, 8 warps (4 m x 2 n), warp tile 32x64.
// K chunks of 64 bf16 in smem, row stride 72 (conflict-free ldmatrix).
// Grid: (MROWS/128, 2 n-halves, 3 sel)
// ---------------------------------------------------------------------------
#define KSTR 72
#define ASZ  (128 * KSTR)              // bf16 elements per tile
#define SM_AH 0
#define SM_AL (ASZ)
#define SM_BH (2 * ASZ)
#define SM_BL (3 * ASZ)
#define QKV_SMEM (4 * ASZ * 2)         // 73728 bytes

__global__ __launch_bounds__(256, 2)
void qkv_mma_kernel(const float* __restrict__ bq,
                    const float* __restrict__ bk,
                    const float* __restrict__ bv)
{
    extern __shared__ __align__(128) __nv_bfloat16 smem[];
    const uint32_t sb = smem_to_u32(smem);

    const int tid  = threadIdx.x;
    const int wid  = tid >> 5;
    const int lane = tid & 31;
    const int wm   = wid & 3;          // 0..3  (m)
    const int wn   = wid >> 2;         // 0..1  (n)

    const int m0  = blockIdx.x * 128;
    const int nb  = blockIdx.y * 128;
    const int sel = blockIdx.z;
    const float* __restrict__ bias = (sel == 0) ? bq : (sel == 1) ? bk : bv;
    float* __restrict__ outp = (sel == 0) ? g_q : (sel == 1) ? g_k : g_v;
    const __nv_bfloat16* __restrict__ xh = (const __nv_bfloat16*)g_xhi;
    const __nv_bfloat16* __restrict__ xl = (const __nv_bfloat16*)g_xlo;
    const __nv_bfloat16* __restrict__ wh = g_wthi + (size_t)sel * CC * CC;
    const __nv_bfloat16* __restrict__ wl = g_wtlo + (size_t)sel * CC * CC;

    float acc[2][8][4];
#pragma unroll
    for (int mt = 0; mt < 2; mt++)
#pragma unroll
        for (int nt = 0; nt < 8; nt++)
#pragma unroll
            for (int j = 0; j < 4; j++) acc[mt][nt][j] = 0.f;

    // per-thread ldmatrix base byte offsets (within a tile)
    const int q  = lane >> 3;          // matrix index 0..3
    const int ri = lane & 7;           // row within matrix
    // A: mats (q&1)-> m-half(+8 rows), (q>>1)-> k-half(+8 cols)
    const uint32_t a_row = (uint32_t)((wm * 32 + (q & 1) * 8 + ri) * (KSTR * 2) + (q >> 1) * 16);
    // B: mats (q>>1)-> n(+8 rows), (q&1)-> k-half(+8 cols)
    const uint32_t b_row = (uint32_t)((wn * 64 + (q >> 1) * 8 + ri) * (KSTR * 2) + (q & 1) * 16);

    for (int ct = 0; ct < 4; ct++) {
        const int kt = ct * 64;
        __syncthreads();
        // load A hi/lo: 128 rows x 64 bf16 (8 chunks of 8 bf16)
#pragma unroll
        for (int it = 0; it < 4; it++) {
            int u = tid + it * 256;            // 0..1023
            int r = u >> 3, c = u & 7;
            size_t src = (size_t)(m0 + r) * CC + kt + c * 8;
            uint32_t d = (uint32_t)(r * KSTR + c * 8);
            *(float4*)&smem[SM_AH + d] = *(const float4*)&xh[src];
            *(float4*)&smem[SM_AL + d] = *(const float4*)&xl[src];
        }
        // load B hi/lo: rows n = nb + r
#pragma unroll
        for (int it = 0; it < 4; it++) {
            int u = tid + it * 256;
            int r = u >> 3, c = u & 7;
            size_t src = (size_t)(nb + r) * CC + kt + c * 8;
            uint32_t d = (uint32_t)(r * KSTR + c * 8);
            *(float4*)&smem[SM_BH + d] = *(const float4*)&wh[src];
            *(float4*)&smem[SM_BL + d] = *(const float4*)&wl[src];
        }
        __syncthreads();

#pragma unroll
        for (int ks = 0; ks < 4; ks++) {
            const uint32_t koff = (uint32_t)(ks * 32);   // 16 bf16 = 32 bytes
            uint32_t ah[2][4], ax[2][4], bh[4][4], bx[4][4];
            // A hi fragments (2 m-tiles)
#pragma unroll
            for (int mt = 0; mt < 2; mt++)
                ldm4(ah[mt], sb + SM_AH * 2 + a_row + (uint32_t)(mt * 16 * KSTR * 2) + koff);
            // B hi fragments (4 n-pairs)
#pragma unroll
            for (int np = 0; np < 4; np++)
                ldm4(bh[np], sb + SM_BH * 2 + b_row + (uint32_t)(np * 16 * KSTR * 2) + koff);
            // hi * hi
#pragma unroll
            for (int mt = 0; mt < 2; mt++)
#pragma unroll
                for (int nt = 0; nt < 8; nt++)
                    mma16816(acc[mt][nt], ah[mt], &bh[nt >> 1][(nt & 1) * 2]);
            // B lo fragments; hi * lo
#pragma unroll
            for (int np = 0; np < 4; np++)
                ldm4(bx[np], sb + SM_BL * 2 + b_row + (uint32_t)(np * 16 * KSTR * 2) + koff);
#pragma unroll
            for (int mt = 0; mt < 2; mt++)
#pragma unroll
                for (int nt = 0; nt < 8; nt++)
                    mma16816(acc[mt][nt], ah[mt], &bx[nt >> 1][(nt & 1) * 2]);
            // A lo fragments; lo * hi
#pragma unroll
            for (int mt = 0; mt < 2; mt++)
                ldm4(ax[mt], sb + SM_AL * 2 + a_row + (uint32_t)(mt * 16 * KSTR * 2) + koff);
#pragma unroll
            for (int mt = 0; mt < 2; mt++)
#pragma unroll
                for (int nt = 0; nt < 8; nt++)
                    mma16816(acc[mt][nt], ax[mt], &bh[nt >> 1][(nt & 1) * 2]);
        }
    }

    // epilogue: +bias, store fp32
    const int g = lane >> 2;
    const int t = lane & 3;
#pragma unroll
    for (int mt = 0; mt < 2; mt++) {
        int row = m0 + wm * 32 + mt * 16 + g;
#pragma unroll
        for (int nt = 0; nt < 8; nt++) {
            int col = nb + wn * 64 + nt * 8 + 2 * t;
            float2 bb = *(const float2*)&bias[col];
            float2 v0, v1;
            v0.x = acc[mt][nt][0] + bb.x;
            v0.y = acc[mt][nt][1] + bb.y;
            v1.x = acc[mt][nt][2] + bb.x;
            v1.y = acc[mt][nt][3] + bb.y;
            *(float2*)&outp[(size_t)row * CC + col] = v0;
            *(float2*)&outp[(size_t)(row + 8) * CC + col] = v1;
        }
    }
}

// ---------------------------------------------------------------------------
// Kernel 2: attention per (b,h) slice + fused residual epilogue. (unchanged)
// ---------------------------------------------------------------------------
#define QSTR 258
#define SSTR 257
#define QTILE_FLOATS (64 * QSTR)
#define STILE_FLOATS (64 * SSTR)
#define SMEM_FLOATS  (2 * QTILE_FLOATS + STILE_FLOATS + 256)
#define SMEM_BYTES   (SMEM_FLOATS * 4)

__device__ __forceinline__ void load_tile(float* __restrict__ dst,
                                          const float* __restrict__ src,
                                          int tid)
{
#pragma unroll
    for (int t = 0; t < 16; t++) {
        int p  = tid + 256 * t;
        int r  = (p >> 3) & 63;
        int c4 = (p & 7) | ((p >> 9) << 3);
        float4 v4 = *(const float4*)&src[(size_t)r * CC + c4 * 4];
        float* d = dst + (size_t)r * QSTR + c4 * 4;
        d[0] = v4.x; d[1] = v4.y; d[2] = v4.z; d[3] = v4.w;
    }
}

__global__ __launch_bounds__(256, 1)
void attn_kernel(const float* __restrict__ xin,
                 const float* __restrict__ gamma,
                 float* __restrict__ out)
{
    extern __shared__ float smemf[];
    float* Qs  = smemf;
    float* KVs = smemf + QTILE_FLOATS;
    float* Ss  = smemf + 2 * QTILE_FLOATS;
    float* red = smemf + 2 * QTILE_FLOATS + STILE_FLOATS;

    const int bh = blockIdx.x;
    const size_t base = (size_t)bh * WW * CC;
    const int tid = threadIdx.x;
    const int tx  = tid & 15;
    const int ty  = tid >> 4;

    for (int qb = 0; qb < 4; qb++) {
        __syncthreads();
        load_tile(Qs, g_q + base + (size_t)qb * 64 * CC, tid);

        for (int kt = 0; kt < 4; kt++) {
            __syncthreads();
            load_tile(KVs, g_k + base + (size_t)kt * 64 * CC, tid);
            __syncthreads();

            u64 acc2[4][4];
#pragma unroll
            for (int i = 0; i < 4; i++)
#pragma unroll
                for (int n = 0; n < 4; n++) acc2[i][n] = 0ull;

#pragma unroll 4
            for (int kk = 0; kk < CC; kk += 2) {
                u64 a2[4], b2[4];
#pragma unroll
                for (int i = 0; i < 4; i++)
                    a2[i] = *(const u64*)&Qs[(ty + 16 * i) * QSTR + kk];
#pragma unroll
                for (int n = 0; n < 4; n++)
                    b2[n] = *(const u64*)&KVs[(tx + 16 * n) * QSTR + kk];
#pragma unroll
                for (int i = 0; i < 4; i++)
#pragma unroll
                    for (int n = 0; n < 4; n++) ffma2(acc2[i][n], a2[i], b2[n]);
            }
#pragma unroll
            for (int i = 0; i < 4; i++)
#pragma unroll
                for (int n = 0; n < 4; n++) {
                    float2 s = unpack2(acc2[i][n]);
                    Ss[(ty + 16 * i) * SSTR + kt * 64 + tx + 16 * n] = s.x + s.y;
                }
        }
        __syncthreads();

        {
            int row = tid & 63;
            int seg = tid >> 6;
            float* srow = Ss + (size_t)row * SSTR + seg * 64;

            float m = -1e30f;
#pragma unroll 8
            for (int c = 0; c < 64; c++) m = fmaxf(m, srow[c]);
            red[seg * 64 + row] = m;
            __syncthreads();
            m = fmaxf(fmaxf(red[row], red[64 + row]),
                      fmaxf(red[128 + row], red[192 + row]));
            __syncthreads();

            float s = 0.f;
#pragma unroll 8
            for (int c = 0; c < 64; c++) {
                float e = __expf(srow[c] - m);
                srow[c] = e;
                s += e;
            }
            red[seg * 64 + row] = s;
            __syncthreads();
            s = red[row] + red[64 + row] + red[128 + row] + red[192 + row];
            float inv = 1.f / s;
#pragma unroll 8
            for (int c = 0; c < 64; c++) srow[c] *= inv;
        }

        u64 oacc2[4][8];
#pragma unroll
        for (int i = 0; i < 4; i++)
#pragma unroll
            for (int n = 0; n < 8; n++) oacc2[i][n] = 0ull;

        for (int jt = 0; jt < 4; jt++) {
            __syncthreads();
            load_tile(KVs, g_v + base + (size_t)jt * 64 * CC, tid);
            __syncthreads();

#pragma unroll 4
            for (int jj = 0; jj < 64; jj++) {
                u64 a2[4], b2[8];
#pragma unroll
                for (int i = 0; i < 4; i++) {
                    float a = Ss[(ty + 16 * i) * SSTR + jt * 64 + jj];
                    a2[i] = pack2(a, a);
                }
#pragma unroll
                for (int n = 0; n < 8; n++)
                    b2[n] = *(const u64*)&KVs[jj * QSTR + 2 * tx + 32 * n];
#pragma unroll
                for (int i = 0; i < 4; i++)
#pragma unroll
                    for (int n = 0; n < 8; n++) ffma2(oacc2[i][n], a2[i], b2[n]);
            }
        }

#pragma unroll
        for (int n = 0; n < 8; n++) {
            int c = 2 * tx + 32 * n;
            float2 g = *(const float2*)&gamma[c];
#pragma unroll
            for (int i = 0; i < 4; i++) {
                size_t off = base + (size_t)(qb * 64 + ty + 16 * i) * CC + c;
                float2 o  = unpack2(oacc2[i][n]);
                float2 xi = *(const float2*)&xin[off];
                float2 r;
                r.x = g.x * o.x + xi.x;
                r.y = g.y * o.y + xi.y;
                *(float2*)&out[off] = r;
            }
        }
    }
}

// ---------------------------------------------------------------------------
extern "C" void kernel_launch(void* const* d_in, const int* in_sizes, int n_in,
                              void* d_out, int out_size)
{
    const float* x     = (const float*)d_in[0];
    const float* wq    = (const float*)d_in[1];
    const float* bq    = (const float*)d_in[2];
    const float* wk    = (const float*)d_in[3];
    const float* bk    = (const float*)d_in[4];
    const float* wv    = (const float*)d_in[5];
    const float* bv    = (const float*)d_in[6];
    const float* gamma = (const float*)d_in[7];
    float* out = (float*)d_out;

    cudaFuncSetAttribute(qkv_mma_kernel,
                         cudaFuncAttributeMaxDynamicSharedMemorySize, QKV_SMEM);
    cudaFuncSetAttribute(attn_kernel,
                         cudaFuncAttributeMaxDynamicSharedMemorySize, SMEM_BYTES);

    // 1) convert x and w to bf16 hi/lo
    cvt_x_kernel<<<(MROWS * CC / 4) / 256, 256>>>(x);
    cvt_w_kernel<<<dim3(CC, 3), CC>>>(wq, wk, wv);

    // 2) QKV projections via warp-mma bf16x3
    qkv_mma_kernel<<<dim3(MROWS / 128, 2, 3), 256, QKV_SMEM>>>(bq, bk, bv);

    // 3) attention + residual (scalar fp32x2)
    attn_kernel<<<NBH, 256, SMEM_BYTES>>>(x, gamma, out);
}

// round 11
// speedup vs baseline: 2.7127x; 1.5372x over previous
#include <cuda_runtime.h>
#include <cuda_bf16.h>
#include <math.h>
#include <stdint.h>

// Problem dims
#define BB 8
#define HH 256
#define WW 256
#define CC 256
#define MROWS (BB*HH*WW)        // 524288 pixel rows
#define NBH   (BB*HH)           // 2048 attention slices

typedef unsigned long long u64;

// ---------------- device scratch (allocation rules: __device__ globals) ------
__device__ __nv_bfloat162 g_xhi[(size_t)MROWS * CC / 2];
__device__ __nv_bfloat162 g_xlo[(size_t)MROWS * CC / 2];
__device__ __nv_bfloat16  g_wthi[3 * CC * CC];   // w^T hi  [sel][n][k]
__device__ __nv_bfloat16  g_wtlo[3 * CC * CC];   // w^T lo
// q,k,v as bf16 hi/lo split (written by qkv_mma_kernel)
__device__ __nv_bfloat16 g_qh[(size_t)MROWS * CC];
__device__ __nv_bfloat16 g_ql[(size_t)MROWS * CC];
__device__ __nv_bfloat16 g_kh[(size_t)MROWS * CC];
__device__ __nv_bfloat16 g_kl[(size_t)MROWS * CC];
__device__ __nv_bfloat16 g_vh[(size_t)MROWS * CC];
__device__ __nv_bfloat16 g_vl[(size_t)MROWS * CC];

// ---------------- warp-mma helpers (baseline PTX, no arch-'a' features) ------
__device__ __forceinline__ uint32_t smem_to_u32(const void* p) {
    uint32_t a;
    asm("{ .reg .u64 t; cvta.to.shared.u64 t, %1; cvt.u32.u64 %0, t; }"
        : "=r"(a) : "l"(p));
    return a;
}
__device__ __forceinline__ void ldm4(uint32_t* r, uint32_t addr) {
    asm volatile("ldmatrix.sync.aligned.m8n8.x4.shared.b16 {%0,%1,%2,%3}, [%4];"
                 : "=r"(r[0]), "=r"(r[1]), "=r"(r[2]), "=r"(r[3]) : "r"(addr));
}
__device__ __forceinline__ void ldm4t(uint32_t* r, uint32_t addr) {
    asm volatile("ldmatrix.sync.aligned.m8n8.x4.trans.shared.b16 {%0,%1,%2,%3}, [%4];"
                 : "=r"(r[0]), "=r"(r[1]), "=r"(r[2]), "=r"(r[3]) : "r"(addr));
}
__device__ __forceinline__ void mma16816(float* c, const uint32_t* a, const uint32_t* b) {
    asm volatile("mma.sync.aligned.m16n8k16.row.col.f32.bf16.bf16.f32 "
                 "{%0,%1,%2,%3}, {%4,%5,%6,%7}, {%8,%9}, {%0,%1,%2,%3};"
                 : "+f"(c[0]), "+f"(c[1]), "+f"(c[2]), "+f"(c[3])
                 : "r"(a[0]), "r"(a[1]), "r"(a[2]), "r"(a[3]),
                   "r"(b[0]), "r"(b[1]));
}
// pack (lo, hi) floats into one bf16x2 register (lo in low 16 bits)
__device__ __forceinline__ uint32_t pk(float lo, float hi) {
    uint32_t r;
    asm("cvt.rn.bf16x2.f32 %0, %1, %2;" : "=r"(r) : "f"(hi), "f"(lo));
    return r;
}

// ---------------------------------------------------------------------------
// Convert kernels: x -> bf16 hi/lo, w -> transposed bf16 hi/lo
// ---------------------------------------------------------------------------
__global__ __launch_bounds__(256)
void cvt_x_kernel(const float* __restrict__ x)
{
    size_t i = (size_t)blockIdx.x * 256 + threadIdx.x;   // float4 index
    float4 v = ((const float4*)x)[i];
    __nv_bfloat16 h0 = __float2bfloat16(v.x);
    __nv_bfloat16 h1 = __float2bfloat16(v.y);
    __nv_bfloat16 h2 = __float2bfloat16(v.z);
    __nv_bfloat16 h3 = __float2bfloat16(v.w);
    __nv_bfloat16 l0 = __float2bfloat16(v.x - __bfloat162float(h0));
    __nv_bfloat16 l1 = __float2bfloat16(v.y - __bfloat162float(h1));
    __nv_bfloat16 l2 = __float2bfloat16(v.z - __bfloat162float(h2));
    __nv_bfloat16 l3 = __float2bfloat16(v.w - __bfloat162float(h3));
    g_xhi[i * 2 + 0] = __halves2bfloat162(h0, h1);
    g_xhi[i * 2 + 1] = __halves2bfloat162(h2, h3);
    g_xlo[i * 2 + 0] = __halves2bfloat162(l0, l1);
    g_xlo[i * 2 + 1] = __halves2bfloat162(l2, l3);
}

__global__ __launch_bounds__(256)
void cvt_w_kernel(const float* __restrict__ wq,
                  const float* __restrict__ wk,
                  const float* __restrict__ wv)
{
    int sel = blockIdx.y;
    const float* w = (sel == 0) ? wq : (sel == 1) ? wk : wv;
    int k = blockIdx.x;          // 0..255
    int n = threadIdx.x;         // 0..255
    float a = w[k * CC + n];     // coalesced read
    __nv_bfloat16 h = __float2bfloat16(a);
    __nv_bfloat16 l = __float2bfloat16(a - __bfloat162float(h));
    g_wthi[sel * CC * CC + n * CC + k] = h;   // transposed store
    g_wtlo[sel * CC * CC + n * CC + k] = l;
}

// ---------------------------------------------------------------------------
// QKV GEMM via warp-level mma.sync (bf16x3 split, fp32 accum).
// CTA: M=128 x N=128, 8 warps (4 m x 2 n), warp tile 32x64.
// Epilogue writes bf16 hi/lo split of q/k/v (consumed by attn_mma_kernel).
// ---------------------------------------------------------------------------
#define KSTR 72
#define ASZ  (128 * KSTR)              // bf16 elements per tile
#define SM_AH 0
#define SM_AL (ASZ)
#define SM_BH (2 * ASZ)
#define SM_BL (3 * ASZ)
#define QKV_SMEM (4 * ASZ * 2)         // 73728 bytes

__device__ __forceinline__ void store_hl(__nv_bfloat16* oh, __nv_bfloat16* ol,
                                         size_t off, float a, float b)
{
    __nv_bfloat16 ha = __float2bfloat16(a);
    __nv_bfloat16 hb = __float2bfloat16(b);
    __nv_bfloat16 la = __float2bfloat16(a - __bfloat162float(ha));
    __nv_bfloat16 lb = __float2bfloat16(b - __bfloat162float(hb));
    *(__nv_bfloat162*)&oh[off] = __halves2bfloat162(ha, hb);
    *(__nv_bfloat162*)&ol[off] = __halves2bfloat162(la, lb);
}

__global__ __launch_bounds__(256, 2)
void qkv_mma_kernel(const float* __restrict__ bq,
                    const float* __restrict__ bk,
                    const float* __restrict__ bv)
{
    extern __shared__ __align__(128) __nv_bfloat16 smem[];
    const uint32_t sb = smem_to_u32(smem);

    const int tid  = threadIdx.x;
    const int wid  = tid >> 5;
    const int lane = tid & 31;
    const int wm   = wid & 3;          // 0..3  (m)
    const int wn   = wid >> 2;         // 0..1  (n)

    const int m0  = blockIdx.x * 128;
    const int nb  = blockIdx.y * 128;
    const int sel = blockIdx.z;
    const float* __restrict__ bias = (sel == 0) ? bq : (sel == 1) ? bk : bv;
    __nv_bfloat16* oh = (sel == 0) ? g_qh : (sel == 1) ? g_kh : g_vh;
    __nv_bfloat16* ol = (sel == 0) ? g_ql : (sel == 1) ? g_kl : g_vl;
    const __nv_bfloat16* __restrict__ xh = (const __nv_bfloat16*)g_xhi;
    const __nv_bfloat16* __restrict__ xl = (const __nv_bfloat16*)g_xlo;
    const __nv_bfloat16* __restrict__ wh = g_wthi + (size_t)sel * CC * CC;
    const __nv_bfloat16* __restrict__ wl = g_wtlo + (size_t)sel * CC * CC;

    float acc[2][8][4];
#pragma unroll
    for (int mt = 0; mt < 2; mt++)
#pragma unroll
        for (int nt = 0; nt < 8; nt++)
#pragma unroll
            for (int j = 0; j < 4; j++) acc[mt][nt][j] = 0.f;

    const int q  = lane >> 3;          // matrix index 0..3
    const int ri = lane & 7;           // row within matrix
    const uint32_t a_row = (uint32_t)((wm * 32 + (q & 1) * 8 + ri) * (KSTR * 2) + (q >> 1) * 16);
    const uint32_t b_row = (uint32_t)((wn * 64 + (q >> 1) * 8 + ri) * (KSTR * 2) + (q & 1) * 16);

    for (int ct = 0; ct < 4; ct++) {
        const int kt = ct * 64;
        __syncthreads();
#pragma unroll
        for (int it = 0; it < 4; it++) {
            int u = tid + it * 256;            // 0..1023
            int r = u >> 3, c = u & 7;
            size_t src = (size_t)(m0 + r) * CC + kt + c * 8;
            uint32_t d = (uint32_t)(r * KSTR + c * 8);
            *(float4*)&smem[SM_AH + d] = *(const float4*)&xh[src];
            *(float4*)&smem[SM_AL + d] = *(const float4*)&xl[src];
        }
#pragma unroll
        for (int it = 0; it < 4; it++) {
            int u = tid + it * 256;
            int r = u >> 3, c = u & 7;
            size_t src = (size_t)(nb + r) * CC + kt + c * 8;
            uint32_t d = (uint32_t)(r * KSTR + c * 8);
            *(float4*)&smem[SM_BH + d] = *(const float4*)&wh[src];
            *(float4*)&smem[SM_BL + d] = *(const float4*)&wl[src];
        }
        __syncthreads();

#pragma unroll
        for (int ks = 0; ks < 4; ks++) {
            const uint32_t koff = (uint32_t)(ks * 32);
            uint32_t ah[2][4], ax[2][4], bh[4][4], bx[4][4];
#pragma unroll
            for (int mt = 0; mt < 2; mt++)
                ldm4(ah[mt], sb + SM_AH * 2 + a_row + (uint32_t)(mt * 16 * KSTR * 2) + koff);
#pragma unroll
            for (int np = 0; np < 4; np++)
                ldm4(bh[np], sb + SM_BH * 2 + b_row + (uint32_t)(np * 16 * KSTR * 2) + koff);
#pragma unroll
            for (int mt = 0; mt < 2; mt++)
#pragma unroll
                for (int nt = 0; nt < 8; nt++)
                    mma16816(acc[mt][nt], ah[mt], &bh[nt >> 1][(nt & 1) * 2]);
#pragma unroll
            for (int np = 0; np < 4; np++)
                ldm4(bx[np], sb + SM_BL * 2 + b_row + (uint32_t)(np * 16 * KSTR * 2) + koff);
#pragma unroll
            for (int mt = 0; mt < 2; mt++)
#pragma unroll
                for (int nt = 0; nt < 8; nt++)
                    mma16816(acc[mt][nt], ah[mt], &bx[nt >> 1][(nt & 1) * 2]);
#pragma unroll
            for (int mt = 0; mt < 2; mt++)
                ldm4(ax[mt], sb + SM_AL * 2 + a_row + (uint32_t)(mt * 16 * KSTR * 2) + koff);
#pragma unroll
            for (int mt = 0; mt < 2; mt++)
#pragma unroll
                for (int nt = 0; nt < 8; nt++)
                    mma16816(acc[mt][nt], ax[mt], &bh[nt >> 1][(nt & 1) * 2]);
        }
    }

    // epilogue: +bias, split to bf16 hi/lo, store
    const int g = lane >> 2;
    const int t = lane & 3;
#pragma unroll
    for (int mt = 0; mt < 2; mt++) {
        int row = m0 + wm * 32 + mt * 16 + g;
#pragma unroll
        for (int nt = 0; nt < 8; nt++) {
            int col = nb + wn * 64 + nt * 8 + 2 * t;
            float2 bb = *(const float2*)&bias[col];
            store_hl(oh, ol, (size_t)row * CC + col,
                     acc[mt][nt][0] + bb.x, acc[mt][nt][1] + bb.y);
            store_hl(oh, ol, (size_t)(row + 8) * CC + col,
                     acc[mt][nt][2] + bb.x, acc[mt][nt][3] + bb.y);
        }
    }
}

// ---------------------------------------------------------------------------
// Attention via mma.sync per (b,h) slice, flash-style register softmax.
// CTA = 1 slice, 8 warps; qb loop over 2 blocks of 128 q-rows; each warp owns
// a 16-row stripe. S = QK^T bf16x3 in register accumulators; softmax via quad
// shfl; P fragments taken directly from S accumulators (bf16 hi); O = P*(Vhi+Vlo).
// ---------------------------------------------------------------------------
#define AT_STR 264                      // bf16 row stride (528B: conflict-free)
#define QH_E 0
#define QL_E 33792                      // 128*264
#define TH_E 67584
#define TL_E 84480                      // +64*264
#define AT_SMEM ((TL_E + 64 * AT_STR) * 2)   // 202752 bytes

__global__ __launch_bounds__(256, 1)
void attn_mma_kernel(const float* __restrict__ xin,
                     const float* __restrict__ gamma,
                     float* __restrict__ out)
{
    extern __shared__ __align__(128) __nv_bfloat16 sm[];
    const uint32_t sb = smem_to_u32(sm);

    const int bh = blockIdx.x;
    const size_t base = (size_t)bh * WW * CC;
    const int tid  = threadIdx.x;
    const int wid  = tid >> 5;
    const int lane = tid & 31;
    const int g  = lane >> 2, t  = lane & 3;
    const int qm = lane >> 3, ri = lane & 7;

    // ldmatrix per-lane addresses
    const uint32_t a_hi = sb + QH_E * 2 +
        (uint32_t)(((wid * 16 + (qm & 1) * 8 + ri) * AT_STR + (qm >> 1) * 8) * 2);
    const uint32_t a_lo = a_hi + (QL_E - QH_E) * 2;
    const uint32_t bk_b = sb + TH_E * 2 +
        (uint32_t)((((qm >> 1) * 8 + ri) * AT_STR + (qm & 1) * 8) * 2);
    const uint32_t bv_b = sb + TH_E * 2 +
        (uint32_t)((((qm & 1) * 8 + ri) * AT_STR + (qm >> 1) * 8) * 2);
    const uint32_t HL = (TL_E - TH_E) * 2;   // hi->lo tile byte distance

    for (int qb = 0; qb < 2; qb++) {
        __syncthreads();
        // ---- load Q block hi/lo: 128 x 256 bf16 each ----
        {
            const __nv_bfloat16* qh = g_qh + base + (size_t)qb * 128 * CC;
            const __nv_bfloat16* ql = g_ql + base + (size_t)qb * 128 * CC;
#pragma unroll
            for (int it = 0; it < 16; it++) {
                int u = tid + it * 256;
                int r = u >> 5, c8 = u & 31;
                *(uint4*)&sm[QH_E + r * AT_STR + c8 * 8] = *(const uint4*)&qh[r * CC + c8 * 8];
                *(uint4*)&sm[QL_E + r * AT_STR + c8 * 8] = *(const uint4*)&ql[r * CC + c8 * 8];
            }
        }

        // ---- S = Q K^T (per warp: 16 rows x 256 keys), bf16x3 ----
        float sacc[32][4];
#pragma unroll
        for (int nt = 0; nt < 32; nt++)
#pragma unroll
            for (int j = 0; j < 4; j++) sacc[nt][j] = 0.f;

#pragma unroll
        for (int kt = 0; kt < 4; kt++) {
            __syncthreads();
            {
                const __nv_bfloat16* kh = g_kh + base + (size_t)kt * 64 * CC;
                const __nv_bfloat16* kl = g_kl + base + (size_t)kt * 64 * CC;
#pragma unroll
                for (int it = 0; it < 8; it++) {
                    int u = tid + it * 256;
                    int r = u >> 5, c8 = u & 31;
                    *(uint4*)&sm[TH_E + r * AT_STR + c8 * 8] = *(const uint4*)&kh[r * CC + c8 * 8];
                    *(uint4*)&sm[TL_E + r * AT_STR + c8 * 8] = *(const uint4*)&kl[r * CC + c8 * 8];
                }
            }
            __syncthreads();

#pragma unroll 2
            for (int kc = 0; kc < 16; kc++) {
                uint32_t ah[4], al[4];
                ldm4(ah, a_hi + kc * 32);
                ldm4(al, a_lo + kc * 32);
#pragma unroll
                for (int jg = 0; jg < 4; jg++) {
                    uint32_t bh4[4], bl4[4];
                    uint32_t ad = bk_b + (uint32_t)(jg * 16 * AT_STR * 2) + kc * 32;
                    ldm4(bh4, ad);
                    ldm4(bl4, ad + HL);
                    float* s0 = sacc[kt * 8 + jg * 2];
                    float* s1 = sacc[kt * 8 + jg * 2 + 1];
                    mma16816(s0, ah, bh4 + 0); mma16816(s1, ah, bh4 + 2);
                    mma16816(s0, ah, bl4 + 0); mma16816(s1, ah, bl4 + 2);
                    mma16816(s0, al, bh4 + 0); mma16816(s1, al, bh4 + 2);
                }
            }
        }

        // ---- softmax (warp-local; rows g and g+8 per thread-quad) ----
        float mx0 = -1e30f, mx1 = -1e30f;
#pragma unroll
        for (int nt = 0; nt < 32; nt++) {
            mx0 = fmaxf(mx0, fmaxf(sacc[nt][0], sacc[nt][1]));
            mx1 = fmaxf(mx1, fmaxf(sacc[nt][2], sacc[nt][3]));
        }
        mx0 = fmaxf(mx0, __shfl_xor_sync(0xffffffffu, mx0, 1));
        mx0 = fmaxf(mx0, __shfl_xor_sync(0xffffffffu, mx0, 2));
        mx1 = fmaxf(mx1, __shfl_xor_sync(0xffffffffu, mx1, 1));
        mx1 = fmaxf(mx1, __shfl_xor_sync(0xffffffffu, mx1, 2));
        float sm0 = 0.f, sm1 = 0.f;
#pragma unroll
        for (int nt = 0; nt < 32; nt++) {
            sacc[nt][0] = __expf(sacc[nt][0] - mx0);
            sacc[nt][1] = __expf(sacc[nt][1] - mx0);
            sacc[nt][2] = __expf(sacc[nt][2] - mx1);
            sacc[nt][3] = __expf(sacc[nt][3] - mx1);
            sm0 += sacc[nt][0] + sacc[nt][1];
            sm1 += sacc[nt][2] + sacc[nt][3];
        }
        sm0 += __shfl_xor_sync(0xffffffffu, sm0, 1);
        sm0 += __shfl_xor_sync(0xffffffffu, sm0, 2);
        sm1 += __shfl_xor_sync(0xffffffffu, sm1, 1);
        sm1 += __shfl_xor_sync(0xffffffffu, sm1, 2);
        const float inv0 = 1.f / sm0, inv1 = 1.f / sm1;

        // ---- pack P fragments straight from S accumulators (A-operand layout) ----
        uint32_t phi[16][4];
#pragma unroll
        for (int m = 0; m < 16; m++) {
            phi[m][0] = pk(sacc[2 * m][0] * inv0,     sacc[2 * m][1] * inv0);
            phi[m][1] = pk(sacc[2 * m][2] * inv1,     sacc[2 * m][3] * inv1);
            phi[m][2] = pk(sacc[2 * m + 1][0] * inv0, sacc[2 * m + 1][1] * inv0);
            phi[m][3] = pk(sacc[2 * m + 1][2] * inv1, sacc[2 * m + 1][3] * inv1);
        }

        // ---- O = P V, c-dimension in two halves (register budget) ----
        for (int ch = 0; ch < 2; ch++) {
            float oacc[16][4];
#pragma unroll
            for (int nt = 0; nt < 16; nt++)
#pragma unroll
                for (int j = 0; j < 4; j++) oacc[nt][j] = 0.f;

#pragma unroll
            for (int vt = 0; vt < 4; vt++) {
                __syncthreads();
                {
                    const __nv_bfloat16* vh = g_vh + base + (size_t)vt * 64 * CC;
                    const __nv_bfloat16* vl = g_vl + base + (size_t)vt * 64 * CC;
#pragma unroll
                    for (int it = 0; it < 8; it++) {
                        int u = tid + it * 256;
                        int r = u >> 5, c8 = u & 31;
                        *(uint4*)&sm[TH_E + r * AT_STR + c8 * 8] = *(const uint4*)&vh[r * CC + c8 * 8];
                        *(uint4*)&sm[TL_E + r * AT_STR + c8 * 8] = *(const uint4*)&vl[r * CC + c8 * 8];
                    }
                }
                __syncthreads();

#pragma unroll
                for (int ml = 0; ml < 4; ml++) {
                    const uint32_t* p = phi[vt * 4 + ml];
#pragma unroll
                    for (int cg = 0; cg < 8; cg++) {
                        uint32_t bh4[4], bl4[4];
                        uint32_t ad = bv_b + (uint32_t)(ml * 16 * AT_STR * 2)
                                    + (uint32_t)((ch * 128 + cg * 16) * 2);
                        ldm4t(bh4, ad);
                        ldm4t(bl4, ad + HL);
                        float* o0 = oacc[cg * 2];
                        float* o1 = oacc[cg * 2 + 1];
                        mma16816(o0, p, bh4 + 0); mma16816(o1, p, bh4 + 2);
                        mma16816(o0, p, bl4 + 0); mma16816(o1, p, bl4 + 2);
                    }
                }
            }

            // ---- epilogue for this c-half: out = gamma * O + x ----
#pragma unroll
            for (int nt = 0; nt < 16; nt++) {
                int c = ch * 128 + nt * 8 + 2 * t;
                float2 gm = *(const float2*)&gamma[c];
                int r0 = qb * 128 + wid * 16 + g;
                size_t o0 = base + (size_t)r0 * CC + c;
                size_t o1 = o0 + (size_t)8 * CC;
                float2 x0 = *(const float2*)&xin[o0];
                float2 x1 = *(const float2*)&xin[o1];
                float2 w0, w1;
                w0.x = gm.x * oacc[nt][0] + x0.x;
                w0.y = gm.y * oacc[nt][1] + x0.y;
                w1.x = gm.x * oacc[nt][2] + x1.x;
                w1.y = gm.y * oacc[nt][3] + x1.y;
                *(float2*)&out[o0] = w0;
                *(float2*)&out[o1] = w1;
            }
        }
    }
}

// ---------------------------------------------------------------------------
extern "C" void kernel_launch(void* const* d_in, const int* in_sizes, int n_in,
                              void* d_out, int out_size)
{
    const float* x     = (const float*)d_in[0];
    const float* wq    = (const float*)d_in[1];
    const float* bq    = (const float*)d_in[2];
    const float* wk    = (const float*)d_in[3];
    const float* bk    = (const float*)d_in[4];
    const float* wv    = (const float*)d_in[5];
    const float* bv    = (const float*)d_in[6];
    const float* gamma = (const float*)d_in[7];
    float* out = (float*)d_out;

    cudaFuncSetAttribute(qkv_mma_kernel,
                         cudaFuncAttributeMaxDynamicSharedMemorySize, QKV_SMEM);
    cudaFuncSetAttribute(attn_mma_kernel,
                         cudaFuncAttributeMaxDynamicSharedMemorySize, AT_SMEM);

    // 1) convert x and w to bf16 hi/lo
    cvt_x_kernel<<<(MROWS * CC / 4) / 256, 256>>>(x);
    cvt_w_kernel<<<dim3(CC, 3), CC>>>(wq, wk, wv);

    // 2) QKV projections via warp-mma bf16x3 -> bf16 hi/lo outputs
    qkv_mma_kernel<<<dim3(MROWS / 128, 2, 3), 256, QKV_SMEM>>>(bq, bk, bv);

    // 3) attention + residual via warp-mma
    attn_mma_kernel<<<NBH, 256, AT_SMEM>>>(x, gamma, out);
}

// round 13
// speedup vs baseline: 3.5313x; 1.3017x over previous
#include <cuda_runtime.h>
#include <cuda_bf16.h>
#include <math.h>
#include <stdint.h>

// Problem dims
#define BB 8
#define HH 256
#define WW 256
#define CC 256
#define MROWS (BB*HH*WW)        // 524288 pixel rows
#define NBH   (BB*HH)           // 2048 attention slices

typedef unsigned long long u64;

// ---------------- device scratch (allocation rules: __device__ globals) ------
__device__ __nv_bfloat162 g_xhi[(size_t)MROWS * CC / 2];
__device__ __nv_bfloat162 g_xlo[(size_t)MROWS * CC / 2];
__device__ __nv_bfloat16  g_wthi[3 * CC * CC];   // w^T hi  [sel][n][k]
__device__ __nv_bfloat16  g_wtlo[3 * CC * CC];   // w^T lo
// q,k as bf16 hi/lo split; v as bf16 hi only (written by qkv_mma_kernel)
__device__ __nv_bfloat16 g_qh[(size_t)MROWS * CC];
__device__ __nv_bfloat16 g_ql[(size_t)MROWS * CC];
__device__ __nv_bfloat16 g_kh[(size_t)MROWS * CC];
__device__ __nv_bfloat16 g_kl[(size_t)MROWS * CC];
__device__ __nv_bfloat16 g_vh[(size_t)MROWS * CC];

// ---------------- warp-mma + cp.async helpers (baseline PTX) -----------------
__device__ __forceinline__ uint32_t smem_to_u32(const void* p) {
    uint32_t a;
    asm("{ .reg .u64 t; cvta.to.shared.u64 t, %1; cvt.u32.u64 %0, t; }"
        : "=r"(a) : "l"(p));
    return a;
}
__device__ __forceinline__ void ldm4(uint32_t* r, uint32_t addr) {
    asm volatile("ldmatrix.sync.aligned.m8n8.x4.shared.b16 {%0,%1,%2,%3}, [%4];"
                 : "=r"(r[0]), "=r"(r[1]), "=r"(r[2]), "=r"(r[3]) : "r"(addr));
}
__device__ __forceinline__ void ldm4t(uint32_t* r, uint32_t addr) {
    asm volatile("ldmatrix.sync.aligned.m8n8.x4.trans.shared.b16 {%0,%1,%2,%3}, [%4];"
                 : "=r"(r[0]), "=r"(r[1]), "=r"(r[2]), "=r"(r[3]) : "r"(addr));
}
__device__ __forceinline__ void mma16816(float* c, const uint32_t* a, const uint32_t* b) {
    asm volatile("mma.sync.aligned.m16n8k16.row.col.f32.bf16.bf16.f32 "
                 "{%0,%1,%2,%3}, {%4,%5,%6,%7}, {%8,%9}, {%0,%1,%2,%3};"
                 : "+f"(c[0]), "+f"(c[1]), "+f"(c[2]), "+f"(c[3])
                 : "r"(a[0]), "r"(a[1]), "r"(a[2]), "r"(a[3]),
                   "r"(b[0]), "r"(b[1]));
}
__device__ __forceinline__ uint32_t pk(float lo, float hi) {
    uint32_t r;
    asm("cvt.rn.bf16x2.f32 %0, %1, %2;" : "=r"(r) : "f"(hi), "f"(lo));
    return r;
}
__device__ __forceinline__ void cpa16(uint32_t s, const void* g) {
    asm volatile("cp.async.cg.shared.global [%0], [%1], 16;"
                 :: "r"(s), "l"(__cvta_generic_to_global(g)));
}
#define CP_COMMIT() asm volatile("cp.async.commit_group;" ::: "memory")
#define CP_WAIT0()  asm volatile("cp.async.wait_group 0;" ::: "memory")
#define CP_WAIT1()  asm volatile("cp.async.wait_group 1;" ::: "memory")

// ---------------------------------------------------------------------------
// Convert kernels: x -> bf16 hi/lo, w -> transposed bf16 hi/lo
// ---------------------------------------------------------------------------
__global__ __launch_bounds__(256)
void cvt_x_kernel(const float* __restrict__ x)
{
    size_t i = (size_t)blockIdx.x * 256 + threadIdx.x;   // float4 index
    float4 v = ((const float4*)x)[i];
    __nv_bfloat16 h0 = __float2bfloat16(v.x);
    __nv_bfloat16 h1 = __float2bfloat16(v.y);
    __nv_bfloat16 h2 = __float2bfloat16(v.z);
    __nv_bfloat16 h3 = __float2bfloat16(v.w);
    __nv_bfloat16 l0 = __float2bfloat16(v.x - __bfloat162float(h0));
    __nv_bfloat16 l1 = __float2bfloat16(v.y - __bfloat162float(h1));
    __nv_bfloat16 l2 = __float2bfloat16(v.z - __bfloat162float(h2));
    __nv_bfloat16 l3 = __float2bfloat16(v.w - __bfloat162float(h3));
    g_xhi[i * 2 + 0] = __halves2bfloat162(h0, h1);
    g_xhi[i * 2 + 1] = __halves2bfloat162(h2, h3);
    g_xlo[i * 2 + 0] = __halves2bfloat162(l0, l1);
    g_xlo[i * 2 + 1] = __halves2bfloat162(l2, l3);
}

__global__ __launch_bounds__(256)
void cvt_w_kernel(const float* __restrict__ wq,
                  const float* __restrict__ wk,
                  const float* __restrict__ wv)
{
    int sel = blockIdx.y;
    const float* w = (sel == 0) ? wq : (sel == 1) ? wk : wv;
    int k = blockIdx.x;          // 0..255
    int n = threadIdx.x;         // 0..255
    float a = w[k * CC + n];     // coalesced read
    __nv_bfloat16 h = __float2bfloat16(a);
    __nv_bfloat16 l = __float2bfloat16(a - __bfloat162float(h));
    g_wthi[sel * CC * CC + n * CC + k] = h;   // transposed store
    g_wtlo[sel * CC * CC + n * CC + k] = l;
}

// ---------------------------------------------------------------------------
// QKV GEMM via warp-level mma.sync.
// q,k: bf16x3 split (hi.hi + hi.lo + lo.hi). v: hi.hi only (consumed as hi).
// CTA: M=128 x N=128, 8 warps (4 m x 2 n), warp tile 32x64.
// ---------------------------------------------------------------------------
#define KSTR 72
#define ASZ  (128 * KSTR)              // bf16 elements per tile
#define SM_AH 0
#define SM_AL (ASZ)
#define SM_BH (2 * ASZ)
#define SM_BL (3 * ASZ)
#define QKV_SMEM (4 * ASZ * 2)         // 73728 bytes

__global__ __launch_bounds__(256, 2)
void qkv_mma_kernel(const float* __restrict__ bq,
                    const float* __restrict__ bk,
                    const float* __restrict__ bv)
{
    extern __shared__ __align__(128) __nv_bfloat16 smem[];
    const uint32_t sb = smem_to_u32(smem);

    const int tid  = threadIdx.x;
    const int wid  = tid >> 5;
    const int lane = tid & 31;
    const int wm   = wid & 3;          // 0..3  (m)
    const int wn   = wid >> 2;         // 0..1  (n)

    const int m0  = blockIdx.x * 128;
    const int nb  = blockIdx.y * 128;
    const int sel = blockIdx.z;
    const float* __restrict__ bias = (sel == 0) ? bq : (sel == 1) ? bk : bv;
    __nv_bfloat16* oh = (sel == 0) ? g_qh : (sel == 1) ? g_kh : g_vh;
    __nv_bfloat16* ol = (sel == 0) ? g_ql : g_kl;   // unused when sel==2
    const bool full = (sel != 2);
    const __nv_bfloat16* __restrict__ xh = (const __nv_bfloat16*)g_xhi;
    const __nv_bfloat16* __restrict__ xl = (const __nv_bfloat16*)g_xlo;
    const __nv_bfloat16* __restrict__ wh = g_wthi + (size_t)sel * CC * CC;
    const __nv_bfloat16* __restrict__ wl = g_wtlo + (size_t)sel * CC * CC;

    float acc[2][8][4];
#pragma unroll
    for (int mt = 0; mt < 2; mt++)
#pragma unroll
        for (int nt = 0; nt < 8; nt++)
#pragma unroll
            for (int j = 0; j < 4; j++) acc[mt][nt][j] = 0.f;

    const int q  = lane >> 3;          // matrix index 0..3
    const int ri = lane & 7;           // row within matrix
    const uint32_t a_row = (uint32_t)((wm * 32 + (q & 1) * 8 + ri) * (KSTR * 2) + (q >> 1) * 16);
    const uint32_t b_row = (uint32_t)((wn * 64 + (q >> 1) * 8 + ri) * (KSTR * 2) + (q & 1) * 16);

    for (int ct = 0; ct < 4; ct++) {
        const int kt = ct * 64;
        __syncthreads();
#pragma unroll
        for (int it = 0; it < 4; it++) {
            int u = tid + it * 256;            // 0..1023
            int r = u >> 3, c = u & 7;
            size_t src = (size_t)(m0 + r) * CC + kt + c * 8;
            uint32_t d = (uint32_t)(r * KSTR + c * 8);
            *(float4*)&smem[SM_AH + d] = *(const float4*)&xh[src];
            if (full) *(float4*)&smem[SM_AL + d] = *(const float4*)&xl[src];
        }
#pragma unroll
        for (int it = 0; it < 4; it++) {
            int u = tid + it * 256;
            int r = u >> 3, c = u & 7;
            size_t src = (size_t)(nb + r) * CC + kt + c * 8;
            uint32_t d = (uint32_t)(r * KSTR + c * 8);
            *(float4*)&smem[SM_BH + d] = *(const float4*)&wh[src];
            if (full) *(float4*)&smem[SM_BL + d] = *(const float4*)&wl[src];
        }
        __syncthreads();

#pragma unroll
        for (int ks = 0; ks < 4; ks++) {
            const uint32_t koff = (uint32_t)(ks * 32);
            uint32_t ah[2][4], ax[2][4], bh[4][4], bx[4][4];
#pragma unroll
            for (int mt = 0; mt < 2; mt++)
                ldm4(ah[mt], sb + SM_AH * 2 + a_row + (uint32_t)(mt * 16 * KSTR * 2) + koff);
#pragma unroll
            for (int np = 0; np < 4; np++)
                ldm4(bh[np], sb + SM_BH * 2 + b_row + (uint32_t)(np * 16 * KSTR * 2) + koff);
#pragma unroll
            for (int mt = 0; mt < 2; mt++)
#pragma unroll
                for (int nt = 0; nt < 8; nt++)
                    mma16816(acc[mt][nt], ah[mt], &bh[nt >> 1][(nt & 1) * 2]);
            if (full) {
#pragma unroll
                for (int np = 0; np < 4; np++)
                    ldm4(bx[np], sb + SM_BL * 2 + b_row + (uint32_t)(np * 16 * KSTR * 2) + koff);
#pragma unroll
                for (int mt = 0; mt < 2; mt++)
#pragma unroll
                    for (int nt = 0; nt < 8; nt++)
                        mma16816(acc[mt][nt], ah[mt], &bx[nt >> 1][(nt & 1) * 2]);
#pragma unroll
                for (int mt = 0; mt < 2; mt++)
                    ldm4(ax[mt], sb + SM_AL * 2 + a_row + (uint32_t)(mt * 16 * KSTR * 2) + koff);
#pragma unroll
                for (int mt = 0; mt < 2; mt++)
#pragma unroll
                    for (int nt = 0; nt < 8; nt++)
                        mma16816(acc[mt][nt], ax[mt], &bh[nt >> 1][(nt & 1) * 2]);
            }
        }
    }

    // epilogue: +bias, split to bf16 hi(/lo), store
    const int g = lane >> 2;
    const int t = lane & 3;
#pragma unroll
    for (int mt = 0; mt < 2; mt++) {
        int row = m0 + wm * 32 + mt * 16 + g;
#pragma unroll
        for (int nt = 0; nt < 8; nt++) {
            int col = nb + wn * 64 + nt * 8 + 2 * t;
            float2 bb = *(const float2*)&bias[col];
#pragma unroll
            for (int h = 0; h < 2; h++) {
                float a = acc[mt][nt][2 * h]     + bb.x;
                float b = acc[mt][nt][2 * h + 1] + bb.y;
                size_t off = (size_t)(row + 8 * h) * CC + col;
                __nv_bfloat16 ha = __float2bfloat16(a);
                __nv_bfloat16 hb = __float2bfloat16(b);
                *(__nv_bfloat162*)&oh[off] = __halves2bfloat162(ha, hb);
                if (full) {
                    __nv_bfloat16 la = __float2bfloat16(a - __bfloat162float(ha));
                    __nv_bfloat16 lb = __float2bfloat16(b - __bfloat162float(hb));
                    *(__nv_bfloat162*)&ol[off] = __halves2bfloat162(la, lb);
                }
            }
        }
    }
}

// ---------------------------------------------------------------------------
// Attention via mma.sync per (b,h) slice, flash-style register softmax.
// S = QK^T bf16x3; softmax via quad shfl; P from S fragments (bf16 hi);
// O = P * V_hi, single pass over c, V double-buffered via cp.async.
// ---------------------------------------------------------------------------
#define AT_STR 264                      // bf16 row stride (528B: conflict-free)
#define QH_E 0
#define QL_E 33792                      // 128*264
#define T0_E 67584                      // K hi  / V buf0  (64*264 elts)
#define T1_E 84480                      // K lo  / V buf1
#define AT_SMEM ((T1_E + 64 * AT_STR) * 2)   // 202752 bytes

__global__ __launch_bounds__(256, 1)
void attn_mma_kernel(const float* __restrict__ xin,
                     const float* __restrict__ gamma,
                     float* __restrict__ out)
{
    extern __shared__ __align__(128) __nv_bfloat16 sm[];
    const uint32_t sb = smem_to_u32(sm);

    const int bh = blockIdx.x;
    const size_t base = (size_t)bh * WW * CC;
    const int tid  = threadIdx.x;
    const int wid  = tid >> 5;
    const int lane = tid & 31;
    const int g  = lane >> 2, t  = lane & 3;
    const int qm = lane >> 3, ri = lane & 7;

    // ldmatrix per-lane addresses
    const uint32_t a_hi = sb +
        (uint32_t)(((wid * 16 + (qm & 1) * 8 + ri) * AT_STR + (qm >> 1) * 8) * 2);
    const uint32_t a_lo = a_hi + QL_E * 2;
    const uint32_t bk_off = (uint32_t)((((qm >> 1) * 8 + ri) * AT_STR + (qm & 1) * 8) * 2);
    const uint32_t bv_off = (uint32_t)((((qm & 1) * 8 + ri) * AT_STR + (qm >> 1) * 8) * 2);
    const uint32_t buf0 = sb + T0_E * 2;
    const uint32_t buf1 = sb + T1_E * 2;

    for (int qb = 0; qb < 2; qb++) {
        __syncthreads();   // previous iteration fully done with T buffers

        // ---- async-load Q block hi/lo (128 x 256) ----
        {
            const __nv_bfloat16* qh = g_qh + base + (size_t)qb * 128 * CC;
            const __nv_bfloat16* ql = g_ql + base + (size_t)qb * 128 * CC;
#pragma unroll
            for (int it = 0; it < 16; it++) {
                int u = tid + it * 256;
                int r = u >> 5, c8 = u & 31;
                uint32_t d = (uint32_t)((r * AT_STR + c8 * 8) * 2);
                cpa16(sb + QH_E * 2 + d, qh + r * CC + c8 * 8);
                cpa16(sb + QL_E * 2 + d, ql + r * CC + c8 * 8);
            }
            CP_COMMIT();
        }
        // ---- async-load K tile 0 (hi->buf0, lo->buf1) ----
        {
            const __nv_bfloat16* kh = g_kh + base;
            const __nv_bfloat16* kl = g_kl + base;
#pragma unroll
            for (int it = 0; it < 8; it++) {
                int u = tid + it * 256;
                int r = u >> 5, c8 = u & 31;
                uint32_t d = (uint32_t)((r * AT_STR + c8 * 8) * 2);
                cpa16(buf0 + d, kh + r * CC + c8 * 8);
                cpa16(buf1 + d, kl + r * CC + c8 * 8);
            }
            CP_COMMIT();
        }

        // ---- S = Q K^T (per warp: 16 rows x 256 keys), bf16x3 ----
        float sacc[32][4];
#pragma unroll
        for (int nt = 0; nt < 32; nt++)
#pragma unroll
            for (int j = 0; j < 4; j++) sacc[nt][j] = 0.f;

        for (int kt = 0; kt < 4; kt++) {
            CP_WAIT0();
            __syncthreads();

#pragma unroll 2
            for (int kc = 0; kc < 16; kc++) {
                uint32_t ah[4], al[4];
                ldm4(ah, a_hi + kc * 32);
                ldm4(al, a_lo + kc * 32);
#pragma unroll
                for (int jg = 0; jg < 4; jg++) {
                    uint32_t bh4[4], bl4[4];
                    uint32_t roff = bk_off + (uint32_t)(jg * 16 * AT_STR * 2) + kc * 32;
                    ldm4(bh4, buf0 + roff);
                    ldm4(bl4, buf1 + roff);
                    float* s0 = sacc[kt * 8 + jg * 2];
                    float* s1 = sacc[kt * 8 + jg * 2 + 1];
                    mma16816(s0, ah, bh4 + 0); mma16816(s1, ah, bh4 + 2);
                    mma16816(s0, ah, bl4 + 0); mma16816(s1, ah, bl4 + 2);
                    mma16816(s0, al, bh4 + 0); mma16816(s1, al, bh4 + 2);
                }
            }
            __syncthreads();
            if (kt < 3) {   // stream next K tile
                const __nv_bfloat16* kh = g_kh + base + (size_t)(kt + 1) * 64 * CC;
                const __nv_bfloat16* kl = g_kl + base + (size_t)(kt + 1) * 64 * CC;
#pragma unroll
                for (int it = 0; it < 8; it++) {
                    int u = tid + it * 256;
                    int r = u >> 5, c8 = u & 31;
                    uint32_t d = (uint32_t)((r * AT_STR + c8 * 8) * 2);
                    cpa16(buf0 + d, kh + r * CC + c8 * 8);
                    cpa16(buf1 + d, kl + r * CC + c8 * 8);
                }
                CP_COMMIT();
            }
        }

        // ---- prefetch V tile 0 into buf0 (overlaps softmax) ----
        {
            const __nv_bfloat16* vh = g_vh + base;
#pragma unroll
            for (int it = 0; it < 8; it++) {
                int u = tid + it * 256;
                int r = u >> 5, c8 = u & 31;
                cpa16(buf0 + (uint32_t)((r * AT_STR + c8 * 8) * 2), vh + r * CC + c8 * 8);
            }
            CP_COMMIT();
        }

        // ---- softmax (warp-local; rows g and g+8 per thread-quad) ----
        float mx0 = -1e30f, mx1 = -1e30f;
#pragma unroll
        for (int nt = 0; nt < 32; nt++) {
            mx0 = fmaxf(mx0, fmaxf(sacc[nt][0], sacc[nt][1]));
            mx1 = fmaxf(mx1, fmaxf(sacc[nt][2], sacc[nt][3]));
        }
        mx0 = fmaxf(mx0, __shfl_xor_sync(0xffffffffu, mx0, 1));
        mx0 = fmaxf(mx0, __shfl_xor_sync(0xffffffffu, mx0, 2));
        mx1 = fmaxf(mx1, __shfl_xor_sync(0xffffffffu, mx1, 1));
        mx1 = fmaxf(mx1, __shfl_xor_sync(0xffffffffu, mx1, 2));
        float sm0 = 0.f, sm1 = 0.f;
#pragma unroll
        for (int nt = 0; nt < 32; nt++) {
            sacc[nt][0] = __expf(sacc[nt][0] - mx0);
            sacc[nt][1] = __expf(sacc[nt][1] - mx0);
            sacc[nt][2] = __expf(sacc[nt][2] - mx1);
            sacc[nt][3] = __expf(sacc[nt][3] - mx1);
            sm0 += sacc[nt][0] + sacc[nt][1];
            sm1 += sacc[nt][2] + sacc[nt][3];
        }
        sm0 += __shfl_xor_sync(0xffffffffu, sm0, 1);
        sm0 += __shfl_xor_sync(0xffffffffu, sm0, 2);
        sm1 += __shfl_xor_sync(0xffffffffu, sm1, 1);
        sm1 += __shfl_xor_sync(0xffffffffu, sm1, 2);
        const float inv0 = 1.f / sm0, inv1 = 1.f / sm1;

        // ---- pack P fragments straight from S accumulators ----
        uint32_t phi[16][4];
#pragma unroll
        for (int m = 0; m < 16; m++) {
            phi[m][0] = pk(sacc[2 * m][0] * inv0,     sacc[2 * m][1] * inv0);
            phi[m][1] = pk(sacc[2 * m][2] * inv1,     sacc[2 * m][3] * inv1);
            phi[m][2] = pk(sacc[2 * m + 1][0] * inv0, sacc[2 * m + 1][1] * inv0);
            phi[m][3] = pk(sacc[2 * m + 1][2] * inv1, sacc[2 * m + 1][3] * inv1);
        }

        // ---- O = P V_hi, single pass, V double-buffered ----
        float oacc[32][4];
#pragma unroll
        for (int nt = 0; nt < 32; nt++)
#pragma unroll
            for (int j = 0; j < 4; j++) oacc[nt][j] = 0.f;

        for (int vt = 0; vt < 4; vt++) {
            if (vt < 3) {   // prefetch next V tile into the other buffer
                const __nv_bfloat16* vh = g_vh + base + (size_t)(vt + 1) * 64 * CC;
                uint32_t nbuf = ((vt + 1) & 1) ? buf1 : buf0;
#pragma unroll
                for (int it = 0; it < 8; it++) {
                    int u = tid + it * 256;
                    int r = u >> 5, c8 = u & 31;
                    cpa16(nbuf + (uint32_t)((r * AT_STR + c8 * 8) * 2), vh + r * CC + c8 * 8);
                }
                CP_COMMIT();
                CP_WAIT1();
            } else {
                CP_WAIT0();
            }
            __syncthreads();

            const uint32_t cbuf = (vt & 1) ? buf1 : buf0;
#pragma unroll
            for (int ml = 0; ml < 4; ml++) {
                const uint32_t* p = phi[vt * 4 + ml];
#pragma unroll
                for (int cg = 0; cg < 16; cg++) {
                    uint32_t bh4[4];
                    ldm4t(bh4, cbuf + bv_off + (uint32_t)(ml * 16 * AT_STR * 2) + cg * 32);
                    mma16816(oacc[cg * 2],     p, bh4 + 0);
                    mma16816(oacc[cg * 2 + 1], p, bh4 + 2);
                }
            }
            __syncthreads();
        }

        // ---- epilogue: out = gamma * O + x ----
#pragma unroll
        for (int nt = 0; nt < 32; nt++) {
            int c = nt * 8 + 2 * t;
            float2 gm = *(const float2*)&gamma[c];
            int r0 = qb * 128 + wid * 16 + g;
            size_t o0 = base + (size_t)r0 * CC + c;
            size_t o1 = o0 + (size_t)8 * CC;
            float2 x0 = *(const float2*)&xin[o0];
            float2 x1 = *(const float2*)&xin[o1];
            float2 w0, w1;
            w0.x = gm.x * oacc[nt][0] + x0.x;
            w0.y = gm.y * oacc[nt][1] + x0.y;
            w1.x = gm.x * oacc[nt][2] + x1.x;
            w1.y = gm.y * oacc[nt][3] + x1.y;
            *(float2*)&out[o0] = w0;
            *(float2*)&out[o1] = w1;
        }
    }
}

// ---------------------------------------------------------------------------
extern "C" void kernel_launch(void* const* d_in, const int* in_sizes, int n_in,
                              void* d_out, int out_size)
{
    const float* x     = (const float*)d_in[0];
    const float* wq    = (const float*)d_in[1];
    const float* bq    = (const float*)d_in[2];
    const float* wk    = (const float*)d_in[3];
    const float* bk    = (const float*)d_in[4];
    const float* wv    = (const float*)d_in[5];
    const float* bv    = (const float*)d_in[6];
    const float* gamma = (const float*)d_in[7];
    float* out = (float*)d_out;

    cudaFuncSetAttribute(qkv_mma_kernel,
                         cudaFuncAttributeMaxDynamicSharedMemorySize, QKV_SMEM);
    cudaFuncSetAttribute(attn_mma_kernel,
                         cudaFuncAttributeMaxDynamicSharedMemorySize, AT_SMEM);

    // 1) convert x and w to bf16 hi/lo
    cvt_x_kernel<<<(MROWS * CC / 4) / 256, 256>>>(x);
    cvt_w_kernel<<<dim3(CC, 3), CC>>>(wq, wk, wv);

    // 2) QKV projections via warp-mma (q,k: bf16x3; v: bf16)
    qkv_mma_kernel<<<dim3(MROWS / 128, 2, 3), 256, QKV_SMEM>>>(bq, bk, bv);

    // 3) attention + residual via warp-mma, cp.async pipelined
    attn_mma_kernel<<<NBH, 256, AT_SMEM>>>(x, gamma, out);
}

// round 14
// speedup vs baseline: 4.2664x; 1.2082x over previous
#include <cuda_runtime.h>
#include <cuda_bf16.h>
#include <math.h>
#include <stdint.h>

// Problem dims
#define BB 8
#define HH 256
#define WW 256
#define CC 256
#define MROWS (BB*HH*WW)        // 524288 pixel rows
#define NBH   (BB*HH)           // 2048 attention slices

typedef unsigned long long u64;

// ---------------- device scratch (allocation rules: __device__ globals) ------
__device__ __nv_bfloat162 g_xhi[(size_t)MROWS * CC / 2];
__device__ __nv_bfloat162 g_xlo[(size_t)MROWS * CC / 2];
// t = x * (Wq Wk^T) as bf16 hi/lo; v = x*Wv + bv as bf16 hi
__device__ __nv_bfloat16 g_th[(size_t)MROWS * CC];
__device__ __nv_bfloat16 g_tl[(size_t)MROWS * CC];
__device__ __nv_bfloat16 g_vh[(size_t)MROWS * CC];
// M^T = (Wq Wk^T)^T in [n][k] layout, bf16 hi/lo; Wv^T hi
__device__ __nv_bfloat16 g_mthi[CC * CC];
__device__ __nv_bfloat16 g_mtlo[CC * CC];
__device__ __nv_bfloat16 g_wvth[CC * CC];
__device__ float g_u[CC];              // Wk * bq
__device__ float g_c[MROWS];           // c_j = x_j . u  (softmax column bias)

// ---------------- warp-mma + cp.async helpers (baseline PTX) -----------------
__device__ __forceinline__ uint32_t smem_to_u32(const void* p) {
    uint32_t a;
    asm("{ .reg .u64 t; cvta.to.shared.u64 t, %1; cvt.u32.u64 %0, t; }"
        : "=r"(a) : "l"(p));
    return a;
}
__device__ __forceinline__ void ldm4(uint32_t* r, uint32_t addr) {
    asm volatile("ldmatrix.sync.aligned.m8n8.x4.shared.b16 {%0,%1,%2,%3}, [%4];"
                 : "=r"(r[0]), "=r"(r[1]), "=r"(r[2]), "=r"(r[3]) : "r"(addr));
}
__device__ __forceinline__ void ldm4t(uint32_t* r, uint32_t addr) {
    asm volatile("ldmatrix.sync.aligned.m8n8.x4.trans.shared.b16 {%0,%1,%2,%3}, [%4];"
                 : "=r"(r[0]), "=r"(r[1]), "=r"(r[2]), "=r"(r[3]) : "r"(addr));
}
__device__ __forceinline__ void mma16816(float* c, const uint32_t* a, const uint32_t* b) {
    asm volatile("mma.sync.aligned.m16n8k16.row.col.f32.bf16.bf16.f32 "
                 "{%0,%1,%2,%3}, {%4,%5,%6,%7}, {%8,%9}, {%0,%1,%2,%3};"
                 : "+f"(c[0]), "+f"(c[1]), "+f"(c[2]), "+f"(c[3])
                 : "r"(a[0]), "r"(a[1]), "r"(a[2]), "r"(a[3]),
                   "r"(b[0]), "r"(b[1]));
}
__device__ __forceinline__ uint32_t pk(float lo, float hi) {
    uint32_t r;
    asm("cvt.rn.bf16x2.f32 %0, %1, %2;" : "=r"(r) : "f"(hi), "f"(lo));
    return r;
}
__device__ __forceinline__ void cpa16(uint32_t s, const void* g) {
    asm volatile("cp.async.cg.shared.global [%0], [%1], 16;"
                 :: "r"(s), "l"(__cvta_generic_to_global(g)));
}
#define CP_COMMIT() asm volatile("cp.async.commit_group;" ::: "memory")
#define CP_WAIT0()  asm volatile("cp.async.wait_group 0;" ::: "memory")
#define CP_WAIT1()  asm volatile("cp.async.wait_group 1;" ::: "memory")

// ---------------------------------------------------------------------------
// prep: M^T[c'][c] = sum_d Wq[c,d]*Wk[c',d]  (fp32, split hi/lo), u = Wk*bq
// block = c' (0..255), thread = c (0..255)
// ---------------------------------------------------------------------------
__global__ __launch_bounds__(256)
void prep_kernel(const float* __restrict__ wq,
                 const float* __restrict__ wk,
                 const float* __restrict__ bq)
{
    __shared__ float wkrow[CC];
    __shared__ float bqs[CC];
    const int cp = blockIdx.x;       // c'
    const int c  = threadIdx.x;      // c
    wkrow[c] = wk[cp * CC + c];      // Wk row c' (coalesced)
    bqs[c]   = bq[c];
    __syncthreads();

    float s = 0.f;
#pragma unroll 8
    for (int d = 0; d < CC; d++)
        s += wq[c * CC + d] * wkrow[d];
    __nv_bfloat16 h = __float2bfloat16(s);
    __nv_bfloat16 l = __float2bfloat16(s - __bfloat162float(h));
    g_mthi[cp * CC + c] = h;
    g_mtlo[cp * CC + c] = l;

    if (cp == 0) {   // u[c] = sum_d Wk[c,d]*bq[d]
        float uu = 0.f;
#pragma unroll 8
        for (int d = 0; d < CC; d++)
            uu += wk[c * CC + d] * bqs[d];
        g_u[c] = uu;
    }
}

// Wv^T hi  (v projection uses hi.hi only)
__global__ __launch_bounds__(256)
void cvt_wv_kernel(const float* __restrict__ wv)
{
    int k = blockIdx.x;          // 0..255
    int n = threadIdx.x;         // 0..255
    g_wvth[n * CC + k] = __float2bfloat16(wv[k * CC + n]);
}

// ---------------------------------------------------------------------------
// cvt_x: x -> bf16 hi/lo, plus c_i = x_i . u  (block = 4 rows of 256)
// ---------------------------------------------------------------------------
__global__ __launch_bounds__(256)
void cvt_x_kernel(const float* __restrict__ x)
{
    __shared__ float red[8];
    const int tid = threadIdx.x;
    size_t i = (size_t)blockIdx.x * 256 + tid;   // float4 index
    float4 v = ((const float4*)x)[i];
    __nv_bfloat16 h0 = __float2bfloat16(v.x);
    __nv_bfloat16 h1 = __float2bfloat16(v.y);
    __nv_bfloat16 h2 = __float2bfloat16(v.z);
    __nv_bfloat16 h3 = __float2bfloat16(v.w);
    __nv_bfloat16 l0 = __float2bfloat16(v.x - __bfloat162float(h0));
    __nv_bfloat16 l1 = __float2bfloat16(v.y - __bfloat162float(h1));
    __nv_bfloat16 l2 = __float2bfloat16(v.z - __bfloat162float(h2));
    __nv_bfloat16 l3 = __float2bfloat16(v.w - __bfloat162float(h3));
    g_xhi[i * 2 + 0] = __halves2bfloat162(h0, h1);
    g_xhi[i * 2 + 1] = __halves2bfloat162(h2, h3);
    g_xlo[i * 2 + 0] = __halves2bfloat162(l0, l1);
    g_xlo[i * 2 + 1] = __halves2bfloat162(l2, l3);

    // c_i = x_i . u  : 64 threads (2 warps) per row
    int col = (tid * 4) & 255;
    float p = v.x * g_u[col] + v.y * g_u[col + 1]
            + v.z * g_u[col + 2] + v.w * g_u[col + 3];
#pragma unroll
    for (int o = 16; o > 0; o >>= 1)
        p += __shfl_xor_sync(0xffffffffu, p, o);
    if ((tid & 31) == 0) red[tid >> 5] = p;
    __syncthreads();
    if (tid < 4)
        g_c[(size_t)blockIdx.x * 4 + tid] = red[2 * tid] + red[2 * tid + 1];
}

// ---------------------------------------------------------------------------
// t/v GEMM via warp-level mma.sync.
// sel 0: t = x * M      (bf16x3: hi.hi + hi.lo + lo.hi), store hi/lo, no bias
// sel 1: v = x * Wv + bv (hi.hi only), store hi
// CTA: M=128 x N=128, 8 warps (4 m x 2 n), warp tile 32x64.
// ---------------------------------------------------------------------------
#define KSTR 72
#define ASZ  (128 * KSTR)              // bf16 elements per tile
#define SM_AH 0
#define SM_AL (ASZ)
#define SM_BH (2 * ASZ)
#define SM_BL (3 * ASZ)
#define QKV_SMEM (4 * ASZ * 2)         // 73728 bytes

__global__ __launch_bounds__(256, 2)
void tv_mma_kernel(const float* __restrict__ bv)
{
    extern __shared__ __align__(128) __nv_bfloat16 smem[];
    const uint32_t sb = smem_to_u32(smem);

    const int tid  = threadIdx.x;
    const int wid  = tid >> 5;
    const int lane = tid & 31;
    const int wm   = wid & 3;          // 0..3  (m)
    const int wn   = wid >> 2;         // 0..1  (n)

    const int m0  = blockIdx.x * 128;
    const int nb  = blockIdx.y * 128;
    const int sel = blockIdx.z;        // 0 = t, 1 = v
    const bool full = (sel == 0);
    __nv_bfloat16* oh = full ? g_th : g_vh;
    __nv_bfloat16* ol = g_tl;
    const __nv_bfloat16* __restrict__ wh = full ? g_mthi : g_wvth;
    const __nv_bfloat16* __restrict__ wl = g_mtlo;
    const __nv_bfloat16* __restrict__ xh = (const __nv_bfloat16*)g_xhi;
    const __nv_bfloat16* __restrict__ xl = (const __nv_bfloat16*)g_xlo;

    float acc[2][8][4];
#pragma unroll
    for (int mt = 0; mt < 2; mt++)
#pragma unroll
        for (int nt = 0; nt < 8; nt++)
#pragma unroll
            for (int j = 0; j < 4; j++) acc[mt][nt][j] = 0.f;

    const int q  = lane >> 3;          // matrix index 0..3
    const int ri = lane & 7;           // row within matrix
    const uint32_t a_row = (uint32_t)((wm * 32 + (q & 1) * 8 + ri) * (KSTR * 2) + (q >> 1) * 16);
    const uint32_t b_row = (uint32_t)((wn * 64 + (q >> 1) * 8 + ri) * (KSTR * 2) + (q & 1) * 16);

    for (int ct = 0; ct < 4; ct++) {
        const int kt = ct * 64;
        __syncthreads();
#pragma unroll
        for (int it = 0; it < 4; it++) {
            int u = tid + it * 256;            // 0..1023
            int r = u >> 3, c = u & 7;
            size_t src = (size_t)(m0 + r) * CC + kt + c * 8;
            uint32_t d = (uint32_t)(r * KSTR + c * 8);
            *(float4*)&smem[SM_AH + d] = *(const float4*)&xh[src];
            if (full) *(float4*)&smem[SM_AL + d] = *(const float4*)&xl[src];
        }
#pragma unroll
        for (int it = 0; it < 4; it++) {
            int u = tid + it * 256;
            int r = u >> 3, c = u & 7;
            size_t src = (size_t)(nb + r) * CC + kt + c * 8;
            uint32_t d = (uint32_t)(r * KSTR + c * 8);
            *(float4*)&smem[SM_BH + d] = *(const float4*)&wh[src];
            if (full) *(float4*)&smem[SM_BL + d] = *(const float4*)&wl[src];
        }
        __syncthreads();

#pragma unroll
        for (int ks = 0; ks < 4; ks++) {
            const uint32_t koff = (uint32_t)(ks * 32);
            uint32_t ah[2][4], ax[2][4], bh[4][4], bx[4][4];
#pragma unroll
            for (int mt = 0; mt < 2; mt++)
                ldm4(ah[mt], sb + SM_AH * 2 + a_row + (uint32_t)(mt * 16 * KSTR * 2) + koff);
#pragma unroll
            for (int np = 0; np < 4; np++)
                ldm4(bh[np], sb + SM_BH * 2 + b_row + (uint32_t)(np * 16 * KSTR * 2) + koff);
#pragma unroll
            for (int mt = 0; mt < 2; mt++)
#pragma unroll
                for (int nt = 0; nt < 8; nt++)
                    mma16816(acc[mt][nt], ah[mt], &bh[nt >> 1][(nt & 1) * 2]);
            if (full) {
#pragma unroll
                for (int np = 0; np < 4; np++)
                    ldm4(bx[np], sb + SM_BL * 2 + b_row + (uint32_t)(np * 16 * KSTR * 2) + koff);
#pragma unroll
                for (int mt = 0; mt < 2; mt++)
#pragma unroll
                    for (int nt = 0; nt < 8; nt++)
                        mma16816(acc[mt][nt], ah[mt], &bx[nt >> 1][(nt & 1) * 2]);
#pragma unroll
                for (int mt = 0; mt < 2; mt++)
                    ldm4(ax[mt], sb + SM_AL * 2 + a_row + (uint32_t)(mt * 16 * KSTR * 2) + koff);
#pragma unroll
                for (int mt = 0; mt < 2; mt++)
#pragma unroll
                    for (int nt = 0; nt < 8; nt++)
                        mma16816(acc[mt][nt], ax[mt], &bh[nt >> 1][(nt & 1) * 2]);
            }
        }
    }

    // epilogue
    const int g = lane >> 2;
    const int t = lane & 3;
#pragma unroll
    for (int mt = 0; mt < 2; mt++) {
        int row = m0 + wm * 32 + mt * 16 + g;
#pragma unroll
        for (int nt = 0; nt < 8; nt++) {
            int col = nb + wn * 64 + nt * 8 + 2 * t;
            float2 bb = full ? make_float2(0.f, 0.f) : *(const float2*)&bv[col];
#pragma unroll
            for (int h = 0; h < 2; h++) {
                float a = acc[mt][nt][2 * h]     + bb.x;
                float b = acc[mt][nt][2 * h + 1] + bb.y;
                size_t off = (size_t)(row + 8 * h) * CC + col;
                __nv_bfloat16 ha = __float2bfloat16(a);
                __nv_bfloat16 hb = __float2bfloat16(b);
                *(__nv_bfloat162*)&oh[off] = __halves2bfloat162(ha, hb);
                if (full) {
                    __nv_bfloat16 la = __float2bfloat16(a - __bfloat162float(ha));
                    __nv_bfloat16 lb = __float2bfloat16(b - __bfloat162float(hb));
                    *(__nv_bfloat162*)&ol[off] = __halves2bfloat162(la, lb);
                }
            }
        }
    }
}

// ---------------------------------------------------------------------------
// Attention via mma.sync per (b,h) slice, flash-style register softmax.
// S = t x^T (bf16x3) + c_j; softmax via quad shfl; P from S fragments;
// O = P * V_hi, single pass over c, V double-buffered via cp.async.
// ---------------------------------------------------------------------------
#define AT_STR 264                      // bf16 row stride (528B: conflict-free)
#define QH_E 0
#define QL_E 33792                      // 128*264
#define T0_E 67584                      // K hi  / V buf0  (64*264 elts)
#define T1_E 84480                      // K lo  / V buf1
#define AT_SMEM ((T1_E + 64 * AT_STR) * 2)   // 202752 bytes
#define AT_SMEM_TOT (AT_SMEM + 1024)         // + c_j slice (256 floats)

__global__ __launch_bounds__(256, 1)
void attn_mma_kernel(const float* __restrict__ xin,
                     const float* __restrict__ gamma,
                     float* __restrict__ out)
{
    extern __shared__ __align__(128) __nv_bfloat16 sm[];
    const uint32_t sb = smem_to_u32(sm);
    float* csm = (float*)((char*)sm + AT_SMEM);

    const int bh = blockIdx.x;
    const size_t base = (size_t)bh * WW * CC;
    const int tid  = threadIdx.x;
    const int wid  = tid >> 5;
    const int lane = tid & 31;
    const int g  = lane >> 2, t  = lane & 3;
    const int qm = lane >> 3, ri = lane & 7;

    csm[tid] = g_c[(size_t)bh * WW + tid];   // softmax column bias slice

    // ldmatrix per-lane addresses
    const uint32_t a_hi = sb +
        (uint32_t)(((wid * 16 + (qm & 1) * 8 + ri) * AT_STR + (qm >> 1) * 8) * 2);
    const uint32_t a_lo = a_hi + QL_E * 2;
    const uint32_t bk_off = (uint32_t)((((qm >> 1) * 8 + ri) * AT_STR + (qm & 1) * 8) * 2);
    const uint32_t bv_off = (uint32_t)((((qm & 1) * 8 + ri) * AT_STR + (qm >> 1) * 8) * 2);
    const uint32_t buf0 = sb + T0_E * 2;
    const uint32_t buf1 = sb + T1_E * 2;

    for (int qb = 0; qb < 2; qb++) {
        __syncthreads();   // previous iteration fully done with T buffers

        // ---- async-load T block hi/lo (128 x 256) : Q-role ----
        {
            const __nv_bfloat16* qh = g_th + base + (size_t)qb * 128 * CC;
            const __nv_bfloat16* ql = g_tl + base + (size_t)qb * 128 * CC;
#pragma unroll
            for (int it = 0; it < 16; it++) {
                int u = tid + it * 256;
                int r = u >> 5, c8 = u & 31;
                uint32_t d = (uint32_t)((r * AT_STR + c8 * 8) * 2);
                cpa16(sb + QH_E * 2 + d, qh + r * CC + c8 * 8);
                cpa16(sb + QL_E * 2 + d, ql + r * CC + c8 * 8);
            }
            CP_COMMIT();
        }
        // ---- async-load x tile 0 (hi->buf0, lo->buf1) : K-role ----
        {
            const __nv_bfloat16* kh = (const __nv_bfloat16*)g_xhi + base;
            const __nv_bfloat16* kl = (const __nv_bfloat16*)g_xlo + base;
#pragma unroll
            for (int it = 0; it < 8; it++) {
                int u = tid + it * 256;
                int r = u >> 5, c8 = u & 31;
                uint32_t d = (uint32_t)((r * AT_STR + c8 * 8) * 2);
                cpa16(buf0 + d, kh + r * CC + c8 * 8);
                cpa16(buf1 + d, kl + r * CC + c8 * 8);
            }
            CP_COMMIT();
        }

        // ---- S = T x^T (per warp: 16 rows x 256 keys), bf16x3 ----
        float sacc[32][4];
#pragma unroll
        for (int nt = 0; nt < 32; nt++)
#pragma unroll
            for (int j = 0; j < 4; j++) sacc[nt][j] = 0.f;

        for (int kt = 0; kt < 4; kt++) {
            CP_WAIT0();
            __syncthreads();

#pragma unroll 2
            for (int kc = 0; kc < 16; kc++) {
                uint32_t ah[4], al[4];
                ldm4(ah, a_hi + kc * 32);
                ldm4(al, a_lo + kc * 32);
#pragma unroll
                for (int jg = 0; jg < 4; jg++) {
                    uint32_t bh4[4], bl4[4];
                    uint32_t roff = bk_off + (uint32_t)(jg * 16 * AT_STR * 2) + kc * 32;
                    ldm4(bh4, buf0 + roff);
                    ldm4(bl4, buf1 + roff);
                    float* s0 = sacc[kt * 8 + jg * 2];
                    float* s1 = sacc[kt * 8 + jg * 2 + 1];
                    mma16816(s0, ah, bh4 + 0); mma16816(s1, ah, bh4 + 2);
                    mma16816(s0, ah, bl4 + 0); mma16816(s1, ah, bl4 + 2);
                    mma16816(s0, al, bh4 + 0); mma16816(s1, al, bh4 + 2);
                }
            }
            __syncthreads();
            if (kt < 3) {   // stream next x tile
                const __nv_bfloat16* kh = (const __nv_bfloat16*)g_xhi + base + (size_t)(kt + 1) * 64 * CC;
                const __nv_bfloat16* kl = (const __nv_bfloat16*)g_xlo + base + (size_t)(kt + 1) * 64 * CC;
#pragma unroll
                for (int it = 0; it < 8; it++) {
                    int u = tid + it * 256;
                    int r = u >> 5, c8 = u & 31;
                    uint32_t d = (uint32_t)((r * AT_STR + c8 * 8) * 2);
                    cpa16(buf0 + d, kh + r * CC + c8 * 8);
                    cpa16(buf1 + d, kl + r * CC + c8 * 8);
                }
                CP_COMMIT();
            }
        }

        // ---- prefetch V tile 0 into buf0 (overlaps softmax) ----
        {
            const __nv_bfloat16* vh = g_vh + base;
#pragma unroll
            for (int it = 0; it < 8; it++) {
                int u = tid + it * 256;
                int r = u >> 5, c8 = u & 31;
                cpa16(buf0 + (uint32_t)((r * AT_STR + c8 * 8) * 2), vh + r * CC + c8 * 8);
            }
            CP_COMMIT();
        }

        // ---- add softmax column bias c_j ----
#pragma unroll
        for (int nt = 0; nt < 32; nt++) {
            float c0 = csm[nt * 8 + 2 * t];
            float c1 = csm[nt * 8 + 2 * t + 1];
            sacc[nt][0] += c0; sacc[nt][1] += c1;
            sacc[nt][2] += c0; sacc[nt][3] += c1;
        }

        // ---- softmax (warp-local; rows g and g+8 per thread-quad) ----
        float mx0 = -1e30f, mx1 = -1e30f;
#pragma unroll
        for (int nt = 0; nt < 32; nt++) {
            mx0 = fmaxf(mx0, fmaxf(sacc[nt][0], sacc[nt][1]));
            mx1 = fmaxf(mx1, fmaxf(sacc[nt][2], sacc[nt][3]));
        }
        mx0 = fmaxf(mx0, __shfl_xor_sync(0xffffffffu, mx0, 1));
        mx0 = fmaxf(mx0, __shfl_xor_sync(0xffffffffu, mx0, 2));
        mx1 = fmaxf(mx1, __shfl_xor_sync(0xffffffffu, mx1, 1));
        mx1 = fmaxf(mx1, __shfl_xor_sync(0xffffffffu, mx1, 2));
        float sm0 = 0.f, sm1 = 0.f;
#pragma unroll
        for (int nt = 0; nt < 32; nt++) {
            sacc[nt][0] = __expf(sacc[nt][0] - mx0);
            sacc[nt][1] = __expf(sacc[nt][1] - mx0);
            sacc[nt][2] = __expf(sacc[nt][2] - mx1);
            sacc[nt][3] = __expf(sacc[nt][3] - mx1);
            sm0 += sacc[nt][0] + sacc[nt][1];
            sm1 += sacc[nt][2] + sacc[nt][3];
        }
        sm0 += __shfl_xor_sync(0xffffffffu, sm0, 1);
        sm0 += __shfl_xor_sync(0xffffffffu, sm0, 2);
        sm1 += __shfl_xor_sync(0xffffffffu, sm1, 1);
        sm1 += __shfl_xor_sync(0xffffffffu, sm1, 2);
        const float inv0 = 1.f / sm0, inv1 = 1.f / sm1;

        // ---- pack P fragments straight from S accumulators ----
        uint32_t phi[16][4];
#pragma unroll
        for (int m = 0; m < 16; m++) {
            phi[m][0] = pk(sacc[2 * m][0] * inv0,     sacc[2 * m][1] * inv0);
            phi[m][1] = pk(sacc[2 * m][2] * inv1,     sacc[2 * m][3] * inv1);
            phi[m][2] = pk(sacc[2 * m + 1][0] * inv0, sacc[2 * m + 1][1] * inv0);
            phi[m][3] = pk(sacc[2 * m + 1][2] * inv1, sacc[2 * m + 1][3] * inv1);
        }

        // ---- O = P V_hi, single pass, V double-buffered ----
        float oacc[32][4];
#pragma unroll
        for (int nt = 0; nt < 32; nt++)
#pragma unroll
            for (int j = 0; j < 4; j++) oacc[nt][j] = 0.f;

        for (int vt = 0; vt < 4; vt++) {
            if (vt < 3) {   // prefetch next V tile into the other buffer
                const __nv_bfloat16* vh = g_vh + base + (size_t)(vt + 1) * 64 * CC;
                uint32_t nbuf = ((vt + 1) & 1) ? buf1 : buf0;
#pragma unroll
                for (int it = 0; it < 8; it++) {
                    int u = tid + it * 256;
                    int r = u >> 5, c8 = u & 31;
                    cpa16(nbuf + (uint32_t)((r * AT_STR + c8 * 8) * 2), vh + r * CC + c8 * 8);
                }
                CP_COMMIT();
                CP_WAIT1();
            } else {
                CP_WAIT0();
            }
            __syncthreads();

            const uint32_t cbuf = (vt & 1) ? buf1 : buf0;
#pragma unroll
            for (int ml = 0; ml < 4; ml++) {
                const uint32_t* p = phi[vt * 4 + ml];
#pragma unroll
                for (int cg = 0; cg < 16; cg++) {
                    uint32_t bh4[4];
                    ldm4t(bh4, cbuf + bv_off + (uint32_t)(ml * 16 * AT_STR * 2) + cg * 32);
                    mma16816(oacc[cg * 2],     p, bh4 + 0);
                    mma16816(oacc[cg * 2 + 1], p, bh4 + 2);
                }
            }
            __syncthreads();
        }

        // ---- epilogue: out = gamma * O + x ----
#pragma unroll
        for (int nt = 0; nt < 32; nt++) {
            int c = nt * 8 + 2 * t;
            float2 gm = *(const float2*)&gamma[c];
            int r0 = qb * 128 + wid * 16 + g;
            size_t o0 = base + (size_t)r0 * CC + c;
            size_t o1 = o0 + (size_t)8 * CC;
            float2 x0 = *(const float2*)&xin[o0];
            float2 x1 = *(const float2*)&xin[o1];
            float2 w0, w1;
            w0.x = gm.x * oacc[nt][0] + x0.x;
            w0.y = gm.y * oacc[nt][1] + x0.y;
            w1.x = gm.x * oacc[nt][2] + x1.x;
            w1.y = gm.y * oacc[nt][3] + x1.y;
            *(float2*)&out[o0] = w0;
            *(float2*)&out[o1] = w1;
        }
    }
}

// ---------------------------------------------------------------------------
extern "C" void kernel_launch(void* const* d_in, const int* in_sizes, int n_in,
                              void* d_out, int out_size)
{
    const float* x     = (const float*)d_in[0];
    const float* wq    = (const float*)d_in[1];
    const float* bq    = (const float*)d_in[2];
    const float* wk    = (const float*)d_in[3];
    const float* wv    = (const float*)d_in[5];
    const float* bv    = (const float*)d_in[6];
    const float* gamma = (const float*)d_in[7];
    float* out = (float*)d_out;

    cudaFuncSetAttribute(tv_mma_kernel,
                         cudaFuncAttributeMaxDynamicSharedMemorySize, QKV_SMEM);
    cudaFuncSetAttribute(attn_mma_kernel,
                         cudaFuncAttributeMaxDynamicSharedMemorySize, AT_SMEM_TOT);

    // 1) M = Wq Wk^T (hi/lo), u = Wk bq ; Wv^T hi
    prep_kernel<<<CC, CC>>>(wq, wk, bq);
    cvt_wv_kernel<<<CC, CC>>>(wv);

    // 2) x -> bf16 hi/lo + c_i = x_i . u   (needs g_u from prep)
    cvt_x_kernel<<<(MROWS * CC / 4) / 256, 256>>>(x);

    // 3) t = x M (bf16x3, hi/lo out); v = x Wv + bv (hi out)
    tv_mma_kernel<<<dim3(MROWS / 128, 2, 2), 256, QKV_SMEM>>>(bv);

    // 4) attention + residual via warp-mma, cp.async pipelined
    attn_mma_kernel<<<NBH, 256, AT_SMEM_TOT>>>(x, gamma, out);
}